// round 9
// baseline (speedup 1.0000x reference)
#include <cuda_runtime.h>
#include <cuda_bf16.h>
#include <math.h>
#include <stdint.h>

// Problem constants
#define NB 16
#define TT 12
#define NN 325
#define D_DIM 128
#define F_DIM 256
#define H_HEADS 8
#define HD 16
#define R_TOTAL (NB*TT*NN)   // 62400
#define M_TILES ((R_TOTAL + 127) / 128)   // 488

// Attention padding
#define NKP 336
#define VT_STRIDE 344        // bf16 per Vt row (172 u32)

// log2(e)/4 folded into q so attention uses plain exp2
#define QSCALE 0.36067376022224085f

// ---------------------------------------------------------------------------
// Scratch (device globals: allocation-guard safe)
// ---------------------------------------------------------------------------
__device__ __nv_bfloat16 g_xb [R_TOTAL * D_DIM];
__device__ __nv_bfloat16 g_qb [R_TOTAL * D_DIM];   // pre-scaled by QSCALE
__device__ __nv_bfloat16 g_kb [R_TOTAL * D_DIM];
__device__ __nv_bfloat16 g_vb [R_TOTAL * D_DIM];
__device__ __nv_bfloat16 g_attb[R_TOTAL * D_DIM];
__device__ __nv_bfloat16 g_hb [R_TOTAL * D_DIM];
__device__ __nv_bfloat16 g_midb[R_TOTAL * F_DIM];
__device__ float         g_h  [R_TOTAL * D_DIM];
__device__ __nv_bfloat16 g_Wqb[D_DIM * D_DIM];
__device__ __nv_bfloat16 g_Wkb[D_DIM * D_DIM];
__device__ __nv_bfloat16 g_Wvb[D_DIM * D_DIM];
__device__ __nv_bfloat16 g_Wob[D_DIM * D_DIM];
__device__ __nv_bfloat16 g_W1b[D_DIM * F_DIM];
__device__ __nv_bfloat16 g_W2b[F_DIM * D_DIM];

// ---------------------------------------------------------------------------
// Common helpers
// ---------------------------------------------------------------------------
__device__ __forceinline__ uint32_t packbf(float x, float y) {  // lo=x, hi=y
    uint32_t r;
    asm("cvt.rn.bf16x2.f32 %0, %1, %2;" : "=r"(r) : "f"(y), "f"(x));
    return r;
}

__device__ __forceinline__ float ex2(float x) {
    float r;
    asm("ex2.approx.f32 %0, %1;" : "=f"(r) : "f"(x));
    return r;
}

__device__ __forceinline__ void mma_bf16(float c[4], const uint32_t a[4], const uint32_t b[2]) {
    asm volatile(
        "mma.sync.aligned.m16n8k16.row.col.f32.bf16.bf16.f32 "
        "{%0,%1,%2,%3}, {%4,%5,%6,%7}, {%8,%9}, {%0,%1,%2,%3};"
        : "+f"(c[0]), "+f"(c[1]), "+f"(c[2]), "+f"(c[3])
        : "r"(a[0]), "r"(a[1]), "r"(a[2]), "r"(a[3]), "r"(b[0]), "r"(b[1]));
}

__device__ __forceinline__ void ldsm_x4(uint32_t r[4], uint32_t addr) {
    asm volatile("ldmatrix.sync.aligned.m8n8.x4.shared.b16 {%0,%1,%2,%3}, [%4];"
        : "=r"(r[0]), "=r"(r[1]), "=r"(r[2]), "=r"(r[3]) : "r"(addr));
}
__device__ __forceinline__ void ldsm_x2(uint32_t r[2], uint32_t addr) {
    asm volatile("ldmatrix.sync.aligned.m8n8.x2.shared.b16 {%0,%1}, [%2];"
        : "=r"(r[0]), "=r"(r[1]) : "r"(addr));
}
__device__ __forceinline__ void ldsm_x2t(uint32_t r[2], uint32_t addr) {
    asm volatile("ldmatrix.sync.aligned.m8n8.x2.trans.shared.b16 {%0,%1}, [%2];"
        : "=r"(r[0]), "=r"(r[1]) : "r"(addr));
}

__device__ __forceinline__ void cp16(uint32_t smaddr, const void* gaddr) {
    asm volatile("cp.async.cg.shared.global [%0], [%1], 16;" :: "r"(smaddr), "l"(gaddr));
}
__device__ __forceinline__ void cp_commit() {
    asm volatile("cp.async.commit_group;");
}
template <int N>
__device__ __forceinline__ void cp_wait() {
    asm volatile("cp.async.wait_group %0;" :: "n"(N));
}

// ---------------------------------------------------------------------------
// GEMM geometry: CTA 128x128, 8 warps (2x4), warp 64x32, 4-stage cp.async.
// ---------------------------------------------------------------------------
#define AS_U32 20
#define BS_U32 68
#define A_STAGE (128 * AS_U32 * 4)          // 10240
#define B_STAGE (32 * BS_U32 * 4)           // 8704
#define STAGE_BYTES (A_STAGE + B_STAGE)     // 18944
#define NSTAGE 4
#define TILE_SMEM (NSTAGE * STAGE_BYTES)    // 75776
#define CS_STRIDE 130
#define LN_SMEM (NSTAGE * STAGE_BYTES)      // 75776 (> 66560 needed for C stage)

// resident-A layout: 128 rows x 128 bf16, row stride 272B
#define ATILE_STRIDE 272
#define ATILE_BYTES (128 * ATILE_STRIDE)    // 34816
#define MP_SMEM (ATILE_BYTES + NSTAGE * B_STAGE) // 69632

// ---- streaming pipeline (projo/ffn2) ----
__device__ __forceinline__ void fill_stage(uint32_t smBase, int s,
                                           const __nv_bfloat16* __restrict__ A, int lda, int row0,
                                           const __nv_bfloat16* __restrict__ B, int ldb, int bcol0,
                                           int kofs) {
    const int tid = threadIdx.x;
    const uint32_t aDst = smBase + s * STAGE_BYTES;
    const uint32_t bDst = aDst + A_STAGE;
    #pragma unroll
    for (int it = 0; it < 2; it++) {
        int idx = tid + it * 256;
        int r = idx >> 2, seg = idx & 3;
        int row = row0 + r;
        if (row > R_TOTAL - 1) row = R_TOTAL - 1;
        cp16(aDst + r * (AS_U32 * 4) + seg * 16,
             A + (size_t)row * lda + kofs + seg * 8);
    }
    #pragma unroll
    for (int it = 0; it < 2; it++) {
        int idx = tid + it * 256;
        int k = idx >> 4, seg = idx & 15;
        cp16(bDst + k * (BS_U32 * 4) + seg * 16,
             B + (size_t)(kofs + k) * ldb + bcol0 + seg * 8);
    }
    cp_commit();
}

__device__ __forceinline__ void gemm_pipe(char* sm,
                                          const __nv_bfloat16* __restrict__ A, int lda, int row0,
                                          const __nv_bfloat16* __restrict__ B, int ldb, int bcol0,
                                          int K, float acc[4][4][4]) {
    const int tid  = threadIdx.x;
    const int warp = tid >> 5;
    const int lane = tid & 31;
    const int wm   = warp >> 2;
    const int wn   = warp & 3;
    const uint32_t smBase = (uint32_t)__cvta_generic_to_shared(sm);

    #pragma unroll
    for (int i = 0; i < 4; i++)
        #pragma unroll
        for (int j = 0; j < 4; j++)
            #pragma unroll
            for (int r = 0; r < 4; r++) acc[i][j][r] = 0.f;

    const int nchunk = K >> 5;
    fill_stage(smBase, 0, A, lda, row0, B, ldb, bcol0, 0);
    if (nchunk > 1) fill_stage(smBase, 1, A, lda, row0, B, ldb, bcol0, 32);
    if (nchunk > 2) fill_stage(smBase, 2, A, lda, row0, B, ldb, bcol0, 64);

    for (int ch = 0; ch < nchunk; ch++) {
        if (ch + 3 < nchunk) {
            fill_stage(smBase, (ch + 3) & 3, A, lda, row0, B, ldb, bcol0, (ch + 3) << 5);
            cp_wait<3>();
        } else if (ch + 2 < nchunk) {
            cp_wait<2>();
        } else if (ch + 1 < nchunk) {
            cp_wait<1>();
        } else {
            cp_wait<0>();
        }
        __syncthreads();

        const uint32_t sa = smBase + (ch & 3) * STAGE_BYTES;
        const uint32_t sb = sa + A_STAGE;
        const uint32_t aBase = sa + (uint32_t)(wm * 64 + (lane & 15)) * (AS_U32 * 4)
                             + ((uint32_t)(lane >> 4) << 4);
        const uint32_t bBase = sb + (uint32_t)(lane & 15) * (BS_U32 * 4) + (uint32_t)wn * 64;

        #pragma unroll
        for (int ks = 0; ks < 2; ks++) {
            uint32_t af[4][4], bfr[4][2];
            #pragma unroll
            for (int mt = 0; mt < 4; mt++)
                ldsm_x4(af[mt], aBase + mt * (16 * AS_U32 * 4) + ks * 32);
            #pragma unroll
            for (int nt = 0; nt < 4; nt++)
                ldsm_x2t(bfr[nt], bBase + ks * (16 * BS_U32 * 4) + nt * 16);
            #pragma unroll
            for (int mt = 0; mt < 4; mt++)
                #pragma unroll
                for (int nt = 0; nt < 4; nt++)
                    mma_bf16(acc[mt][nt], af[mt], bfr[nt]);
        }
        __syncthreads();
    }
}

// ---- resident-A helpers (qkv / ffn1) ----
__device__ __forceinline__ void fill_A_tile(uint32_t aTile,
                                            const __nv_bfloat16* __restrict__ A, int row0) {
    const int tid = threadIdx.x;
    #pragma unroll
    for (int it = 0; it < 8; it++) {
        int idx = tid + it * 256;
        int r = idx >> 4, seg = idx & 15;
        int row = row0 + r;
        if (row > R_TOTAL - 1) row = R_TOTAL - 1;
        cp16(aTile + r * ATILE_STRIDE + seg * 16,
             A + (size_t)row * D_DIM + seg * 8);
    }
}

__device__ __forceinline__ void fill_Bchunk(uint32_t dst,
                                            const __nv_bfloat16* __restrict__ B, int ldb,
                                            int bcol0, int kofs) {
    const int tid = threadIdx.x;
    #pragma unroll
    for (int it = 0; it < 2; it++) {
        int idx = tid + it * 256;
        int k = idx >> 4, seg = idx & 15;
        cp16(dst + k * (BS_U32 * 4) + seg * 16,
             B + (size_t)(kofs + k) * ldb + bcol0 + seg * 8);
    }
    cp_commit();
}

__device__ __forceinline__ void mma_chunk_resA(uint32_t aTile, uint32_t bStage, int ch,
                                               float acc[4][4][4], int wm, int wn, int lane) {
    const uint32_t aBase = aTile + (uint32_t)(wm * 64 + (lane & 15)) * ATILE_STRIDE
                         + (uint32_t)(ch * 64) + ((uint32_t)(lane >> 4) << 4);
    const uint32_t bBase = bStage + (uint32_t)(lane & 15) * (BS_U32 * 4) + (uint32_t)wn * 64;
    #pragma unroll
    for (int ks = 0; ks < 2; ks++) {
        uint32_t af[4][4], bfr[4][2];
        #pragma unroll
        for (int mt = 0; mt < 4; mt++)
            ldsm_x4(af[mt], aBase + mt * (16 * ATILE_STRIDE) + ks * 32);
        #pragma unroll
        for (int nt = 0; nt < 4; nt++)
            ldsm_x2t(bfr[nt], bBase + ks * (16 * BS_U32 * 4) + nt * 16);
        #pragma unroll
        for (int mt = 0; mt < 4; mt++)
            #pragma unroll
            for (int nt = 0; nt < 4; nt++)
                mma_bf16(acc[mt][nt], af[mt], bfr[nt]);
    }
}

// Stage accumulators to smem C[128][130] for row-wise epilogues.
__device__ __forceinline__ void stage_c(float* smf, float acc[4][4][4]) {
    const int tid  = threadIdx.x;
    const int warp = tid >> 5;
    const int lane = tid & 31;
    const int gid  = lane >> 2;
    const int tig  = lane & 3;
    const int wm   = warp >> 2;
    const int wn   = warp & 3;
    #pragma unroll
    for (int mt = 0; mt < 4; mt++) {
        #pragma unroll
        for (int nt = 0; nt < 4; nt++) {
            int row = wm * 64 + mt * 16 + gid;
            int col = wn * 32 + nt * 8 + (tig << 1);
            *(float2*)(smf + row * CS_STRIDE + col)       = make_float2(acc[mt][nt][0], acc[mt][nt][1]);
            *(float2*)(smf + (row + 8) * CS_STRIDE + col) = make_float2(acc[mt][nt][2], acc[mt][nt][3]);
        }
    }
    __syncthreads();
}

// ---------------------------------------------------------------------------
// Conversion kernels (fp32 -> bf16)
// ---------------------------------------------------------------------------
__global__ void k_cvt_x(const float* __restrict__ x) {
    uint32_t* dst = (uint32_t*)g_xb;
    const int n4 = R_TOTAL * D_DIM / 4;
    for (int i = blockIdx.x * blockDim.x + threadIdx.x; i < n4; i += gridDim.x * blockDim.x) {
        float4 v = *(const float4*)(x + (size_t)i * 4);
        dst[i * 2]     = packbf(v.x, v.y);
        dst[i * 2 + 1] = packbf(v.z, v.w);
    }
}

__global__ void k_cvt_w(const float* __restrict__ Wq, const float* __restrict__ Wk,
                        const float* __restrict__ Wv, const float* __restrict__ Wo,
                        const float* __restrict__ W1, const float* __restrict__ W2) {
    const int n4 = (4 * 16384 + 2 * 32768) / 4;   // 32768
    for (int i = blockIdx.x * blockDim.x + threadIdx.x; i < n4; i += gridDim.x * blockDim.x) {
        const float* src;
        __nv_bfloat16* dst;
        int off;
        if      (i < 4096)  { src = Wq; dst = g_Wqb; off = i; }
        else if (i < 8192)  { src = Wk; dst = g_Wkb; off = i - 4096; }
        else if (i < 12288) { src = Wv; dst = g_Wvb; off = i - 8192; }
        else if (i < 16384) { src = Wo; dst = g_Wob; off = i - 12288; }
        else if (i < 24576) { src = W1; dst = g_W1b; off = i - 16384; }
        else                { src = W2; dst = g_W2b; off = i - 24576; }
        float4 v = *(const float4*)(src + (size_t)off * 4);
        uint32_t* d = (uint32_t*)dst + off * 2;
        d[0] = packbf(v.x, v.y);
        d[1] = packbf(v.z, v.w);
    }
}

// ---------------------------------------------------------------------------
// Kernel 1: QKV — resident A (x tile), streams Wq,Wk,Wv; 4-stage B pipe.
// ---------------------------------------------------------------------------
__global__ void __launch_bounds__(256) k_qkv(const float* __restrict__ bq,
                                             const float* __restrict__ bk,
                                             const float* __restrict__ bv) {
    extern __shared__ char sm[];
    const uint32_t smB = (uint32_t)__cvta_generic_to_shared(sm);
    const uint32_t aTile = smB;
    const uint32_t bst0 = smB + ATILE_BYTES;
    const int row0 = blockIdx.x << 7;

    const int tid  = threadIdx.x;
    const int warp = tid >> 5;
    const int lane = tid & 31;
    const int gid  = lane >> 2;
    const int tig  = lane & 3;
    const int wm   = warp >> 2;
    const int wn   = warp & 3;

    fill_A_tile(aTile, g_xb, row0);
    fill_Bchunk(bst0,               g_Wqb, D_DIM, 0, 0);    // group: A + B0
    fill_Bchunk(bst0 + B_STAGE,     g_Wqb, D_DIM, 0, 32);
    fill_Bchunk(bst0 + 2 * B_STAGE, g_Wqb, D_DIM, 0, 64);

    float acc[4][4][4];
    #pragma unroll
    for (int i = 0; i < 4; i++)
        #pragma unroll
        for (int j = 0; j < 4; j++)
            #pragma unroll
            for (int r = 0; r < 4; r++) acc[i][j][r] = 0.f;

    for (int t = 0; t < 12; t++) {
        const int ch = t & 3, w = t >> 2;
        if (t + 3 < 12) {
            const int t3 = t + 3;
            const __nv_bfloat16* Bn = ((t3 >> 2) == 0) ? g_Wqb : ((t3 >> 2) == 1) ? g_Wkb : g_Wvb;
            fill_Bchunk(bst0 + (t3 & 3) * B_STAGE, Bn, D_DIM, 0, (t3 & 3) << 5);
            cp_wait<3>();
        } else if (t + 2 < 12) {
            cp_wait<2>();
        } else if (t + 1 < 12) {
            cp_wait<1>();
        } else {
            cp_wait<0>();
        }
        __syncthreads();
        mma_chunk_resA(aTile, bst0 + (t & 3) * B_STAGE, ch, acc, wm, wn, lane);
        __syncthreads();

        if (ch == 3) {
            const float* bias   = (w == 0) ? bq : (w == 1) ? bk : bv;
            __nv_bfloat16* out  = (w == 0) ? g_qb : (w == 1) ? g_kb : g_vb;
            const float scale   = (w == 0) ? QSCALE : 1.f;
            #pragma unroll
            for (int mt = 0; mt < 4; mt++) {
                int r0 = row0 + wm * 64 + mt * 16 + gid;
                int r1 = r0 + 8;
                #pragma unroll
                for (int nt = 0; nt < 4; nt++) {
                    int col = wn * 32 + nt * 8 + (tig << 1);
                    float b0 = bias[col], b1 = bias[col + 1];
                    if (r0 < R_TOTAL)
                        *(uint32_t*)(out + (size_t)r0 * D_DIM + col) =
                            packbf((acc[mt][nt][0] + b0) * scale, (acc[mt][nt][1] + b1) * scale);
                    if (r1 < R_TOTAL)
                        *(uint32_t*)(out + (size_t)r1 * D_DIM + col) =
                            packbf((acc[mt][nt][2] + b0) * scale, (acc[mt][nt][3] + b1) * scale);
                    acc[mt][nt][0] = acc[mt][nt][1] = acc[mt][nt][2] = acc[mt][nt][3] = 0.f;
                }
            }
        }
    }
}

// ---------------------------------------------------------------------------
// Kernel 2: attention per (b,h,t). grid = 1536, block = 256.
// Each warp batches its 3 m-tiles (w, w+8, w+16; padded to 24) so K/V/ones
// fragments are loaded ONCE per j per warp. Pad-tile outputs never stored.
// SBUF layout (u32): Qs[384*8]=3072, Ks[336*12]=4032, Vt[24*172]=4128.
// ---------------------------------------------------------------------------
#define QS_OFF 0
#define KS_OFF 3072
#define VT_OFF 7104
#define SBUF_U32 11232

__global__ void __launch_bounds__(256) attn_kernel() {
    __shared__ __align__(16) uint32_t SBUF[SBUF_U32];

    const int bid = blockIdx.x;
    const int t = bid % TT;
    const int h = (bid / TT) % H_HEADS;
    const int b = bid / (TT * H_HEADS);
    const int row0 = (b * TT + t) * NN;
    const int hoff = h * HD;
    const int tid = threadIdx.x;

    __nv_bfloat16* Vtb = (__nv_bfloat16*)(SBUF + VT_OFF);

    // Fill Q/K/V^T
    for (int idx = tid; idx < NKP * 2; idx += 256) {
        int m = idx >> 1;
        int seg = idx & 1;
        uint4 qv, kv, vv;
        if (m < NN) {
            size_t base = (size_t)(row0 + m) * D_DIM + hoff + seg * 8;
            qv = *(const uint4*)(g_qb + base);
            kv = *(const uint4*)(g_kb + base);
            vv = *(const uint4*)(g_vb + base);
        } else {
            qv = kv = vv = make_uint4(0, 0, 0, 0);
        }
        *(uint4*)(SBUF + QS_OFF + m * 8 + seg * 4) = qv;
        *(uint4*)(SBUF + KS_OFF + m * 12 + seg * 4) = kv;
        int d0 = seg * 8;
        uint32_t vu[4] = {vv.x, vv.y, vv.z, vv.w};
        #pragma unroll
        for (int j = 0; j < 4; j++) {
            __nv_bfloat162 p = *(__nv_bfloat162*)&vu[j];
            Vtb[(d0 + 2 * j)     * VT_STRIDE + m] = p.x;
            Vtb[(d0 + 2 * j + 1) * VT_STRIDE + m] = p.y;
        }
    }
    // Zero Q pad rows (336-383) so pad tiles are deterministic
    for (int i = tid; i < 384; i += 256)
        SBUF[QS_OFF + NKP * 8 + i] = 0;
    // Ones row (Vt row 16) for m<NN; rows 17-23 zero
    for (int i = tid; i < 8 * (VT_STRIDE / 2); i += 256) {
        int r = 16 + i / (VT_STRIDE / 2);
        int cu = i % (VT_STRIDE / 2);
        int m = cu * 2;
        uint32_t val = 0;
        if (r == 16) {
            if (m + 1 < NN)      val = 0x3F803F80u;
            else if (m < NN)     val = 0x00003F80u;
        }
        SBUF[VT_OFF + r * (VT_STRIDE / 2) + cu] = val;
    }
    __syncthreads();

    const int warp = tid >> 5;
    const int lane = tid & 31;
    const int gid  = lane >> 2;
    const int tig  = lane & 3;

    // per-lane ldmatrix bases
    const int rowInTile = (lane & 7) + ((lane >> 4) << 3);
    const uint32_t off16 = (uint32_t)(lane & 8) << 1;
    const uint32_t ksSm = (uint32_t)__cvta_generic_to_shared(SBUF + KS_OFF);
    const uint32_t vtSm = (uint32_t)__cvta_generic_to_shared(SBUF + VT_OFF);
    const uint32_t kLane  = ksSm + (uint32_t)rowInTile * 48 + off16;
    const uint32_t vLane  = vtSm + (uint32_t)rowInTile * (VT_STRIDE * 2) + off16;
    const uint32_t v1Lane = vtSm + (uint32_t)(16 + (lane & 7)) * (VT_STRIDE * 2) + off16;

    // Load Q fragments for this warp's 3 tiles
    uint32_t qa[3][4];
    #pragma unroll
    for (int tt = 0; tt < 3; tt++) {
        int m0 = (warp + 8 * tt) << 4;
        qa[tt][0] = SBUF[QS_OFF + (m0 + gid) * 8 + tig];
        qa[tt][1] = SBUF[QS_OFF + (m0 + gid + 8) * 8 + tig];
        qa[tt][2] = SBUF[QS_OFF + (m0 + gid) * 8 + tig + 4];
        qa[tt][3] = SBUF[QS_OFF + (m0 + gid + 8) * 8 + tig + 4];
    }

    float oc0[3][4], oc1[3][4], oc2[3][4];
    #pragma unroll
    for (int tt = 0; tt < 3; tt++)
        #pragma unroll
        for (int r = 0; r < 4; r++) { oc0[tt][r] = 0.f; oc1[tt][r] = 0.f; oc2[tt][r] = 0.f; }

    for (int j = 0; j < 21; j++) {
        uint32_t kr[4];
        ldsm_x4(kr, kLane + (uint32_t)j * (16 * 48));

        uint32_t pa[3][4];
        #pragma unroll
        for (int tt = 0; tt < 3; tt++) {
            float c0[4] = {0.f, 0.f, 0.f, 0.f};
            float c1[4] = {0.f, 0.f, 0.f, 0.f};
            mma_bf16(c0, qa[tt], kr);
            mma_bf16(c1, qa[tt], kr + 2);
            pa[tt][0] = packbf(ex2(c0[0]), ex2(c0[1]));
            pa[tt][1] = packbf(ex2(c0[2]), ex2(c0[3]));
            pa[tt][2] = packbf(ex2(c1[0]), ex2(c1[1]));
            pa[tt][3] = packbf(ex2(c1[2]), ex2(c1[3]));
        }

        uint32_t vr[4], v1r[2];
        ldsm_x4(vr, vLane + (uint32_t)j * 32);
        ldsm_x2(v1r, v1Lane + (uint32_t)j * 32);
        #pragma unroll
        for (int tt = 0; tt < 3; tt++) {
            mma_bf16(oc0[tt], pa[tt], vr);
            mma_bf16(oc1[tt], pa[tt], vr + 2);
            mma_bf16(oc2[tt], pa[tt], v1r);
        }
    }

    #pragma unroll
    for (int tt = 0; tt < 3; tt++) {
        float rs0 = __shfl_sync(0xffffffffu, oc2[tt][0], lane & ~3);
        float rs1 = __shfl_sync(0xffffffffu, oc2[tt][2], lane & ~3);
        float i0 = 1.f / rs0;
        float i1 = 1.f / rs1;
        int m0 = (warp + 8 * tt) << 4;
        int r0 = m0 + gid;
        int r1 = m0 + gid + 8;
        if (r0 < NN) {
            __nv_bfloat16* op = g_attb + (size_t)(row0 + r0) * D_DIM + hoff;
            *(uint32_t*)(op + 2 * tig)     = packbf(oc0[tt][0] * i0, oc0[tt][1] * i0);
            *(uint32_t*)(op + 8 + 2 * tig) = packbf(oc1[tt][0] * i0, oc1[tt][1] * i0);
        }
        if (r1 < NN) {
            __nv_bfloat16* op = g_attb + (size_t)(row0 + r1) * D_DIM + hoff;
            *(uint32_t*)(op + 2 * tig)     = packbf(oc0[tt][2] * i1, oc0[tt][3] * i1);
            *(uint32_t*)(op + 8 + 2 * tig) = packbf(oc1[tt][2] * i1, oc1[tt][3] * i1);
        }
    }
}

// ---------------------------------------------------------------------------
// Kernel 3: h = LN1(x + att @ Wo + bo); writes g_h (fp32) + g_hb (bf16).
// ---------------------------------------------------------------------------
__global__ void __launch_bounds__(256) k_projo_ln1(const float* __restrict__ x,
                                                   const float* __restrict__ bo,
                                                   const float* __restrict__ g1, const float* __restrict__ b1) {
    extern __shared__ char sm[];
    float* smf = (float*)sm;
    const int row0 = blockIdx.x << 7;

    float acc[4][4][4];
    gemm_pipe(sm, g_attb, D_DIM, row0, g_Wob, D_DIM, 0, D_DIM, acc);
    stage_c(smf, acc);

    const int tid = threadIdx.x;
    if (tid < 128) {
        int row = row0 + tid;
        if (row < R_TOTAL) {
            const float* Cr = smf + tid * CS_STRIDE;
            const float* xr = x + (size_t)row * D_DIM;
            float s1 = 0.f, s2 = 0.f;
            #pragma unroll
            for (int c = 0; c < 128; c++) {
                float v = Cr[c] + bo[c] + xr[c];
                s1 += v; s2 += v * v;
            }
            float mean = s1 * (1.f / 128.f);
            float var  = s2 * (1.f / 128.f) - mean * mean;
            float rstd = rsqrtf(var + 1e-5f);
            float* hr = g_h + (size_t)row * D_DIM;
            uint32_t* hb = (uint32_t*)(g_hb + (size_t)row * D_DIM);
            #pragma unroll
            for (int c = 0; c < 128; c += 4) {
                float4 o;
                o.x = (Cr[c]     + bo[c]     + xr[c]     - mean) * rstd * g1[c]     + b1[c];
                o.y = (Cr[c + 1] + bo[c + 1] + xr[c + 1] - mean) * rstd * g1[c + 1] + b1[c + 1];
                o.z = (Cr[c + 2] + bo[c + 2] + xr[c + 2] - mean) * rstd * g1[c + 2] + b1[c + 2];
                o.w = (Cr[c + 3] + bo[c + 3] + xr[c + 3] - mean) * rstd * g1[c + 3] + b1[c + 3];
                *(float4*)(hr + c) = o;
                hb[c >> 1]       = packbf(o.x, o.y);
                hb[(c >> 1) + 1] = packbf(o.z, o.w);
            }
        }
    }
}

// ---------------------------------------------------------------------------
// Kernel 4: mid = gelu(h @ W1 + b1) — resident A, 4-stage B pipe. grid 488.
// ---------------------------------------------------------------------------
__global__ void __launch_bounds__(256) k_ffn1(const float* __restrict__ b1) {
    extern __shared__ char sm[];
    const uint32_t smB = (uint32_t)__cvta_generic_to_shared(sm);
    const uint32_t aTile = smB;
    const uint32_t bst0 = smB + ATILE_BYTES;
    const int row0 = blockIdx.x << 7;

    const int tid  = threadIdx.x;
    const int warp = tid >> 5;
    const int lane = tid & 31;
    const int gid  = lane >> 2;
    const int tig  = lane & 3;
    const int wm   = warp >> 2;
    const int wn   = warp & 3;

    fill_A_tile(aTile, g_hb, row0);
    fill_Bchunk(bst0,               g_W1b, F_DIM, 0, 0);
    fill_Bchunk(bst0 + B_STAGE,     g_W1b, F_DIM, 0, 32);
    fill_Bchunk(bst0 + 2 * B_STAGE, g_W1b, F_DIM, 0, 64);

    float acc[4][4][4];
    #pragma unroll
    for (int i = 0; i < 4; i++)
        #pragma unroll
        for (int j = 0; j < 4; j++)
            #pragma unroll
            for (int r = 0; r < 4; r++) acc[i][j][r] = 0.f;

    for (int t = 0; t < 8; t++) {
        const int ch = t & 3, w = t >> 2;
        if (t + 3 < 8) {
            const int t3 = t + 3;
            fill_Bchunk(bst0 + (t3 & 3) * B_STAGE, g_W1b, F_DIM,
                        (t3 >> 2) << 7, (t3 & 3) << 5);
            cp_wait<3>();
        } else if (t + 2 < 8) {
            cp_wait<2>();
        } else if (t + 1 < 8) {
            cp_wait<1>();
        } else {
            cp_wait<0>();
        }
        __syncthreads();
        mma_chunk_resA(aTile, bst0 + (t & 3) * B_STAGE, ch, acc, wm, wn, lane);
        __syncthreads();

        if (ch == 3) {
            const int col0 = w << 7;
            #pragma unroll
            for (int mt = 0; mt < 4; mt++) {
                int r0 = row0 + wm * 64 + mt * 16 + gid;
                int r1 = r0 + 8;
                #pragma unroll
                for (int nt = 0; nt < 4; nt++) {
                    int col = col0 + wn * 32 + nt * 8 + (tig << 1);
                    float b0 = b1[col], bb1 = b1[col + 1];
                    float v0 = acc[mt][nt][0] + b0;
                    float v1 = acc[mt][nt][1] + bb1;
                    float v2 = acc[mt][nt][2] + b0;
                    float v3 = acc[mt][nt][3] + bb1;
                    float e0 = 0.5f * v0 * (1.f + erff(v0 * 0.70710678118654752f));
                    float e1 = 0.5f * v1 * (1.f + erff(v1 * 0.70710678118654752f));
                    float e2 = 0.5f * v2 * (1.f + erff(v2 * 0.70710678118654752f));
                    float e3 = 0.5f * v3 * (1.f + erff(v3 * 0.70710678118654752f));
                    if (r0 < R_TOTAL)
                        *(uint32_t*)(g_midb + (size_t)r0 * F_DIM + col) = packbf(e0, e1);
                    if (r1 < R_TOTAL)
                        *(uint32_t*)(g_midb + (size_t)r1 * F_DIM + col) = packbf(e2, e3);
                    acc[mt][nt][0] = acc[mt][nt][1] = acc[mt][nt][2] = acc[mt][nt][3] = 0.f;
                }
            }
        }
    }
}

// ---------------------------------------------------------------------------
// Kernel 5: out = LN2(h + mid @ W2 + b2). grid 488, block 256. K=256.
// ---------------------------------------------------------------------------
__global__ void __launch_bounds__(256) k_ffn2_ln2(const float* __restrict__ b2,
                                                  const float* __restrict__ g2,
                                                  const float* __restrict__ bt2,
                                                  float* __restrict__ out) {
    extern __shared__ char sm[];
    float* smf = (float*)sm;
    const int row0 = blockIdx.x << 7;

    float acc[4][4][4];
    gemm_pipe(sm, g_midb, F_DIM, row0, g_W2b, D_DIM, 0, F_DIM, acc);
    stage_c(smf, acc);

    const int tid = threadIdx.x;
    if (tid < 128) {
        int row = row0 + tid;
        if (row < R_TOTAL) {
            const float* Cr = smf + tid * CS_STRIDE;
            const float* hr = g_h + (size_t)row * D_DIM;
            float s1 = 0.f, s2 = 0.f;
            #pragma unroll
            for (int c = 0; c < 128; c++) {
                float v = Cr[c] + b2[c] + hr[c];
                s1 += v; s2 += v * v;
            }
            float mean = s1 * (1.f / 128.f);
            float var  = s2 * (1.f / 128.f) - mean * mean;
            float rstd = rsqrtf(var + 1e-5f);
            float* orow = out + (size_t)row * D_DIM;
            #pragma unroll
            for (int c = 0; c < 128; c += 4) {
                float4 o;
                o.x = (Cr[c]     + b2[c]     + hr[c]     - mean) * rstd * g2[c]     + bt2[c];
                o.y = (Cr[c + 1] + b2[c + 1] + hr[c + 1] - mean) * rstd * g2[c + 1] + bt2[c + 1];
                o.z = (Cr[c + 2] + b2[c + 2] + hr[c + 2] - mean) * rstd * g2[c + 2] + bt2[c + 2];
                o.w = (Cr[c + 3] + b2[c + 3] + hr[c + 3] - mean) * rstd * g2[c + 3] + bt2[c + 3];
                *(float4*)(orow + c) = o;
            }
        }
    }
}

// ---------------------------------------------------------------------------
extern "C" void kernel_launch(void* const* d_in, const int* in_sizes, int n_in,
                              void* d_out, int out_size) {
    const float* x     = (const float*)d_in[0];
    const float* Wq    = (const float*)d_in[1];
    const float* bq    = (const float*)d_in[2];
    const float* Wk    = (const float*)d_in[3];
    const float* bk    = (const float*)d_in[4];
    const float* Wv    = (const float*)d_in[5];
    const float* bv    = (const float*)d_in[6];
    const float* Wo    = (const float*)d_in[7];
    const float* bo    = (const float*)d_in[8];
    const float* ln1_g = (const float*)d_in[9];
    const float* ln1_b = (const float*)d_in[10];
    const float* W1    = (const float*)d_in[11];
    const float* b1    = (const float*)d_in[12];
    const float* W2    = (const float*)d_in[13];
    const float* b2    = (const float*)d_in[14];
    const float* ln2_g = (const float*)d_in[15];
    const float* ln2_b = (const float*)d_in[16];
    float* out = (float*)d_out;

    cudaFuncSetAttribute(k_qkv,       cudaFuncAttributeMaxDynamicSharedMemorySize, MP_SMEM);
    cudaFuncSetAttribute(k_ffn1,      cudaFuncAttributeMaxDynamicSharedMemorySize, MP_SMEM);
    cudaFuncSetAttribute(k_projo_ln1, cudaFuncAttributeMaxDynamicSharedMemorySize, LN_SMEM);
    cudaFuncSetAttribute(k_ffn2_ln2,  cudaFuncAttributeMaxDynamicSharedMemorySize, LN_SMEM);

    k_cvt_w<<<64, 512>>>(Wq, Wk, Wv, Wo, W1, W2);
    k_cvt_x<<<1024, 512>>>(x);
    k_qkv<<<M_TILES, 256, MP_SMEM>>>(bq, bk, bv);
    attn_kernel<<<NB * H_HEADS * TT, 256>>>();
    k_projo_ln1<<<M_TILES, 256, LN_SMEM>>>(x, bo, ln1_g, ln1_b);
    k_ffn1<<<M_TILES, 256, MP_SMEM>>>(b1);
    k_ffn2_ln2<<<M_TILES, 256, LN_SMEM>>>(b2, ln2_g, ln2_b, out);
}

// round 10
// speedup vs baseline: 1.0193x; 1.0193x over previous
#include <cuda_runtime.h>
#include <cuda_bf16.h>
#include <math.h>
#include <stdint.h>

// Problem constants
#define NB 16
#define TT 12
#define NN 325
#define D_DIM 128
#define F_DIM 256
#define H_HEADS 8
#define HD 16
#define R_TOTAL (NB*TT*NN)   // 62400
#define M_TILES ((R_TOTAL + 127) / 128)   // 488

// Attention padding
#define NKP 336
#define VT_STRIDE 344

// log2(e)/4 folded into q so attention uses plain exp2
#define QSCALE 0.36067376022224085f

// ---------------------------------------------------------------------------
// Scratch (device globals: allocation-guard safe)
// ---------------------------------------------------------------------------
__device__ __nv_bfloat16 g_xb [R_TOTAL * D_DIM];
__device__ __nv_bfloat16 g_qb [R_TOTAL * D_DIM];   // pre-scaled by QSCALE
__device__ __nv_bfloat16 g_kb [R_TOTAL * D_DIM];
__device__ __nv_bfloat16 g_vb [R_TOTAL * D_DIM];
__device__ __nv_bfloat16 g_attb[R_TOTAL * D_DIM];
__device__ __nv_bfloat16 g_hb [R_TOTAL * D_DIM];
__device__ __nv_bfloat16 g_midb[R_TOTAL * F_DIM];
__device__ float         g_h  [R_TOTAL * D_DIM];
__device__ __nv_bfloat16 g_Wqb[D_DIM * D_DIM];
__device__ __nv_bfloat16 g_Wkb[D_DIM * D_DIM];
__device__ __nv_bfloat16 g_Wvb[D_DIM * D_DIM];
__device__ __nv_bfloat16 g_Wob[D_DIM * D_DIM];
__device__ __nv_bfloat16 g_W1b[D_DIM * F_DIM];
__device__ __nv_bfloat16 g_W2b[F_DIM * D_DIM];

// ---------------------------------------------------------------------------
// Common helpers
// ---------------------------------------------------------------------------
__device__ __forceinline__ uint32_t packbf(float x, float y) {  // lo=x, hi=y
    uint32_t r;
    asm("cvt.rn.bf16x2.f32 %0, %1, %2;" : "=r"(r) : "f"(y), "f"(x));
    return r;
}

__device__ __forceinline__ float ex2(float x) {
    float r;
    asm("ex2.approx.f32 %0, %1;" : "=f"(r) : "f"(x));
    return r;
}

__device__ __forceinline__ void mma_bf16(float c[4], const uint32_t a[4], const uint32_t b[2]) {
    asm volatile(
        "mma.sync.aligned.m16n8k16.row.col.f32.bf16.bf16.f32 "
        "{%0,%1,%2,%3}, {%4,%5,%6,%7}, {%8,%9}, {%0,%1,%2,%3};"
        : "+f"(c[0]), "+f"(c[1]), "+f"(c[2]), "+f"(c[3])
        : "r"(a[0]), "r"(a[1]), "r"(a[2]), "r"(a[3]), "r"(b[0]), "r"(b[1]));
}

__device__ __forceinline__ void ldsm_x4(uint32_t r[4], uint32_t addr) {
    asm volatile("ldmatrix.sync.aligned.m8n8.x4.shared.b16 {%0,%1,%2,%3}, [%4];"
        : "=r"(r[0]), "=r"(r[1]), "=r"(r[2]), "=r"(r[3]) : "r"(addr));
}
__device__ __forceinline__ void ldsm_x2(uint32_t r[2], uint32_t addr) {
    asm volatile("ldmatrix.sync.aligned.m8n8.x2.shared.b16 {%0,%1}, [%2];"
        : "=r"(r[0]), "=r"(r[1]) : "r"(addr));
}
__device__ __forceinline__ void ldsm_x2t(uint32_t r[2], uint32_t addr) {
    asm volatile("ldmatrix.sync.aligned.m8n8.x2.trans.shared.b16 {%0,%1}, [%2];"
        : "=r"(r[0]), "=r"(r[1]) : "r"(addr));
}

__device__ __forceinline__ void cp16(uint32_t smaddr, const void* gaddr) {
    asm volatile("cp.async.cg.shared.global [%0], [%1], 16;" :: "r"(smaddr), "l"(gaddr));
}
__device__ __forceinline__ void cp_commit() {
    asm volatile("cp.async.commit_group;");
}
template <int N>
__device__ __forceinline__ void cp_wait() {
    asm volatile("cp.async.wait_group %0;" :: "n"(N));
}

// ---------------------------------------------------------------------------
// Resident-operand GEMM geometry: CTA 128x128 out tile, 8 warps (2x4),
// warp 64x32. A tile resident (stride 272B), ALL B chunks resident.
// Mainloop is barrier-free.
// ---------------------------------------------------------------------------
#define BS_U32 68
#define B_SLOT (32 * BS_U32 * 4)            // 8704 bytes per 32-k B chunk
#define ATILE_STRIDE 272
#define ATILE_BYTES (128 * ATILE_STRIDE)    // 34816
#define CS_STRIDE 130
#define C_BYTES (128 * CS_STRIDE * 4)       // 66560

#define QKV_SMEM  (ATILE_BYTES + 12 * B_SLOT)            // 139264
#define FFN1_SMEM (ATILE_BYTES + 8 * B_SLOT)             // 104448
#define PROJO_SMEM (ATILE_BYTES + 4 * B_SLOT)            // 69632 (>= C_BYTES)
#define FFN2_SMEM (2 * ATILE_BYTES + 8 * B_SLOT)         // 139264 (>= C_BYTES)

// Fill resident A tile: 128 rows x 128 bf16 from A[row][colofs..colofs+128)
__device__ __forceinline__ void fill_A_tile(uint32_t aTile,
                                            const __nv_bfloat16* __restrict__ A,
                                            int lda, int row0, int colofs) {
    const int tid = threadIdx.x;
    #pragma unroll
    for (int it = 0; it < 8; it++) {
        int idx = tid + it * 256;
        int r = idx >> 4, seg = idx & 15;
        int row = row0 + r;
        if (row > R_TOTAL - 1) row = R_TOTAL - 1;
        cp16(aTile + r * ATILE_STRIDE + seg * 16,
             A + (size_t)row * lda + colofs + seg * 8);
    }
}

// Fill one 32-k B chunk (no commit)
__device__ __forceinline__ void fill_Bchunk(uint32_t dst,
                                            const __nv_bfloat16* __restrict__ B, int ldb,
                                            int bcol0, int kofs) {
    const int tid = threadIdx.x;
    #pragma unroll
    for (int it = 0; it < 2; it++) {
        int idx = tid + it * 256;
        int k = idx >> 4, seg = idx & 15;
        cp16(dst + k * (BS_U32 * 4) + seg * 16,
             B + (size_t)(kofs + k) * ldb + bcol0 + seg * 8);
    }
}

// One 32-k chunk of MMAs from resident A (+ column offset ch*64B) and B slot.
__device__ __forceinline__ void mma_chunk(uint32_t aTile, uint32_t bSlot, int ch,
                                          float acc[4][4][4], int wm, int wn, int lane) {
    const uint32_t aBase = aTile + (uint32_t)(wm * 64 + (lane & 15)) * ATILE_STRIDE
                         + (uint32_t)(ch * 64) + ((uint32_t)(lane >> 4) << 4);
    const uint32_t bBase = bSlot + (uint32_t)(lane & 15) * (BS_U32 * 4) + (uint32_t)wn * 64;
    #pragma unroll
    for (int ks = 0; ks < 2; ks++) {
        uint32_t af[4][4], bfr[4][2];
        #pragma unroll
        for (int mt = 0; mt < 4; mt++)
            ldsm_x4(af[mt], aBase + mt * (16 * ATILE_STRIDE) + ks * 32);
        #pragma unroll
        for (int nt = 0; nt < 4; nt++)
            ldsm_x2t(bfr[nt], bBase + ks * (16 * BS_U32 * 4) + nt * 16);
        #pragma unroll
        for (int mt = 0; mt < 4; mt++)
            #pragma unroll
            for (int nt = 0; nt < 4; nt++)
                mma_bf16(acc[mt][nt], af[mt], bfr[nt]);
    }
}

__device__ __forceinline__ void zero_acc(float acc[4][4][4]) {
    #pragma unroll
    for (int i = 0; i < 4; i++)
        #pragma unroll
        for (int j = 0; j < 4; j++)
            #pragma unroll
            for (int r = 0; r < 4; r++) acc[i][j][r] = 0.f;
}

// Stage accumulators to smem C[128][130] for row-wise epilogues.
__device__ __forceinline__ void stage_c(float* smf, float acc[4][4][4]) {
    const int tid  = threadIdx.x;
    const int warp = tid >> 5;
    const int lane = tid & 31;
    const int gid  = lane >> 2;
    const int tig  = lane & 3;
    const int wm   = warp >> 2;
    const int wn   = warp & 3;
    #pragma unroll
    for (int mt = 0; mt < 4; mt++) {
        #pragma unroll
        for (int nt = 0; nt < 4; nt++) {
            int row = wm * 64 + mt * 16 + gid;
            int col = wn * 32 + nt * 8 + (tig << 1);
            *(float2*)(smf + row * CS_STRIDE + col)       = make_float2(acc[mt][nt][0], acc[mt][nt][1]);
            *(float2*)(smf + (row + 8) * CS_STRIDE + col) = make_float2(acc[mt][nt][2], acc[mt][nt][3]);
        }
    }
    __syncthreads();
}

// ---------------------------------------------------------------------------
// Conversion kernels (fp32 -> bf16)
// ---------------------------------------------------------------------------
__global__ void k_cvt_x(const float* __restrict__ x) {
    uint32_t* dst = (uint32_t*)g_xb;
    const int n4 = R_TOTAL * D_DIM / 4;
    for (int i = blockIdx.x * blockDim.x + threadIdx.x; i < n4; i += gridDim.x * blockDim.x) {
        float4 v = *(const float4*)(x + (size_t)i * 4);
        dst[i * 2]     = packbf(v.x, v.y);
        dst[i * 2 + 1] = packbf(v.z, v.w);
    }
}

__global__ void k_cvt_w(const float* __restrict__ Wq, const float* __restrict__ Wk,
                        const float* __restrict__ Wv, const float* __restrict__ Wo,
                        const float* __restrict__ W1, const float* __restrict__ W2) {
    const int n4 = (4 * 16384 + 2 * 32768) / 4;   // 32768
    for (int i = blockIdx.x * blockDim.x + threadIdx.x; i < n4; i += gridDim.x * blockDim.x) {
        const float* src;
        __nv_bfloat16* dst;
        int off;
        if      (i < 4096)  { src = Wq; dst = g_Wqb; off = i; }
        else if (i < 8192)  { src = Wk; dst = g_Wkb; off = i - 4096; }
        else if (i < 12288) { src = Wv; dst = g_Wvb; off = i - 8192; }
        else if (i < 16384) { src = Wo; dst = g_Wob; off = i - 12288; }
        else if (i < 24576) { src = W1; dst = g_W1b; off = i - 16384; }
        else                { src = W2; dst = g_W2b; off = i - 24576; }
        float4 v = *(const float4*)(src + (size_t)off * 4);
        uint32_t* d = (uint32_t*)dst + off * 2;
        d[0] = packbf(v.x, v.y);
        d[1] = packbf(v.z, v.w);
    }
}

// ---------------------------------------------------------------------------
// Kernel 1: QKV — A resident, all 3 weights resident (12 B slots), no
// mainloop barriers. grid 488, block 256.
// ---------------------------------------------------------------------------
__global__ void __launch_bounds__(256) k_qkv(const float* __restrict__ bq,
                                             const float* __restrict__ bk,
                                             const float* __restrict__ bv) {
    extern __shared__ char sm[];
    const uint32_t smB = (uint32_t)__cvta_generic_to_shared(sm);
    const uint32_t aTile = smB;
    const uint32_t bBase = smB + ATILE_BYTES;
    const int row0 = blockIdx.x << 7;

    const int tid  = threadIdx.x;
    const int warp = tid >> 5;
    const int lane = tid & 31;
    const int gid  = lane >> 2;
    const int tig  = lane & 3;
    const int wm   = warp >> 2;
    const int wn   = warp & 3;

    fill_A_tile(aTile, g_xb, D_DIM, row0, 0);
    #pragma unroll
    for (int s = 0; s < 12; s++) {
        const __nv_bfloat16* W = (s < 4) ? g_Wqb : (s < 8) ? g_Wkb : g_Wvb;
        fill_Bchunk(bBase + s * B_SLOT, W, D_DIM, 0, (s & 3) << 5);
    }
    cp_commit();
    cp_wait<0>();
    __syncthreads();

    float acc[4][4][4];
    #pragma unroll
    for (int w = 0; w < 3; w++) {
        zero_acc(acc);
        #pragma unroll
        for (int ch = 0; ch < 4; ch++)
            mma_chunk(aTile, bBase + (w * 4 + ch) * B_SLOT, ch, acc, wm, wn, lane);

        const float* bias   = (w == 0) ? bq : (w == 1) ? bk : bv;
        __nv_bfloat16* out  = (w == 0) ? g_qb : (w == 1) ? g_kb : g_vb;
        const float scale   = (w == 0) ? QSCALE : 1.f;
        #pragma unroll
        for (int mt = 0; mt < 4; mt++) {
            int r0 = row0 + wm * 64 + mt * 16 + gid;
            int r1 = r0 + 8;
            #pragma unroll
            for (int nt = 0; nt < 4; nt++) {
                int col = wn * 32 + nt * 8 + (tig << 1);
                float b0 = bias[col], b1 = bias[col + 1];
                if (r0 < R_TOTAL)
                    *(uint32_t*)(out + (size_t)r0 * D_DIM + col) =
                        packbf((acc[mt][nt][0] + b0) * scale, (acc[mt][nt][1] + b1) * scale);
                if (r1 < R_TOTAL)
                    *(uint32_t*)(out + (size_t)r1 * D_DIM + col) =
                        packbf((acc[mt][nt][2] + b0) * scale, (acc[mt][nt][3] + b1) * scale);
            }
        }
    }
}

// ---------------------------------------------------------------------------
// Kernel 2: attention per (b,h,t). grid = 1536, block = 256. (R8 version)
// ---------------------------------------------------------------------------
__global__ void __launch_bounds__(256) attn_kernel() {
    __shared__ __align__(16) uint32_t Qs[NKP * 8];
    __shared__ __align__(16) uint32_t Ks[NKP * 12];
    __shared__ __align__(16) uint32_t Vt[24 * (VT_STRIDE / 2)];

    const int bid = blockIdx.x;
    const int t = bid % TT;
    const int h = (bid / TT) % H_HEADS;
    const int b = bid / (TT * H_HEADS);
    const int row0 = (b * TT + t) * NN;
    const int hoff = h * HD;
    const int tid = threadIdx.x;

    __nv_bfloat16* Vtb = (__nv_bfloat16*)Vt;

    for (int idx = tid; idx < NKP * 2; idx += 256) {
        int m = idx >> 1;
        int seg = idx & 1;
        uint4 qv, kv, vv;
        if (m < NN) {
            size_t base = (size_t)(row0 + m) * D_DIM + hoff + seg * 8;
            qv = *(const uint4*)(g_qb + base);
            kv = *(const uint4*)(g_kb + base);
            vv = *(const uint4*)(g_vb + base);
        } else {
            qv = kv = vv = make_uint4(0, 0, 0, 0);
        }
        *(uint4*)(Qs + m * 8 + seg * 4) = qv;
        *(uint4*)(Ks + m * 12 + seg * 4) = kv;
        int d0 = seg * 8;
        uint32_t vu[4] = {vv.x, vv.y, vv.z, vv.w};
        #pragma unroll
        for (int j = 0; j < 4; j++) {
            __nv_bfloat162 p = *(__nv_bfloat162*)&vu[j];
            Vtb[(d0 + 2 * j)     * VT_STRIDE + m] = p.x;
            Vtb[(d0 + 2 * j + 1) * VT_STRIDE + m] = p.y;
        }
    }
    for (int i = tid; i < 8 * (VT_STRIDE / 2); i += 256) {
        int r = 16 + i / (VT_STRIDE / 2);
        int cu = i % (VT_STRIDE / 2);
        int m = cu * 2;
        uint32_t val = 0;
        if (r == 16) {
            if (m + 1 < NN)      val = 0x3F803F80u;
            else if (m < NN)     val = 0x00003F80u;
        }
        Vt[r * (VT_STRIDE / 2) + cu] = val;
    }
    __syncthreads();

    const int warp = tid >> 5;
    const int lane = tid & 31;
    const int gid  = lane >> 2;
    const int tig  = lane & 3;

    const int rowInTile = (lane & 7) + ((lane >> 4) << 3);
    const uint32_t off16 = (uint32_t)(lane & 8) << 1;
    const uint32_t ksSm = (uint32_t)__cvta_generic_to_shared(Ks);
    const uint32_t vtSm = (uint32_t)__cvta_generic_to_shared(Vt);
    const uint32_t kLane  = ksSm + (uint32_t)rowInTile * 48 + off16;
    const uint32_t vLane  = vtSm + (uint32_t)rowInTile * (VT_STRIDE * 2) + off16;
    const uint32_t v1Lane = vtSm + (uint32_t)(16 + (lane & 7)) * (VT_STRIDE * 2) + off16;

    for (int mt = warp; mt < 21; mt += 8) {
        const int m0 = mt << 4;
        uint32_t qa[4];
        qa[0] = Qs[(m0 + gid) * 8 + tig];
        qa[1] = Qs[(m0 + gid + 8) * 8 + tig];
        qa[2] = Qs[(m0 + gid) * 8 + tig + 4];
        qa[3] = Qs[(m0 + gid + 8) * 8 + tig + 4];

        float oc0[4] = {0.f, 0.f, 0.f, 0.f};
        float oc1[4] = {0.f, 0.f, 0.f, 0.f};
        float oc2[4] = {0.f, 0.f, 0.f, 0.f};

        for (int j = 0; j < 21; j++) {
            float c0[4] = {0.f, 0.f, 0.f, 0.f};
            float c1[4] = {0.f, 0.f, 0.f, 0.f};
            uint32_t kr[4];
            ldsm_x4(kr, kLane + (uint32_t)j * (16 * 48));
            mma_bf16(c0, qa, kr);
            mma_bf16(c1, qa, kr + 2);

            float p00 = ex2(c0[0]);
            float p01 = ex2(c0[1]);
            float p02 = ex2(c0[2]);
            float p03 = ex2(c0[3]);
            float p10 = ex2(c1[0]);
            float p11 = ex2(c1[1]);
            float p12 = ex2(c1[2]);
            float p13 = ex2(c1[3]);

            uint32_t pa[4];
            pa[0] = packbf(p00, p01);
            pa[1] = packbf(p02, p03);
            pa[2] = packbf(p10, p11);
            pa[3] = packbf(p12, p13);

            uint32_t vr[4], v1r[2];
            ldsm_x4(vr, vLane + (uint32_t)j * 32);
            ldsm_x2(v1r, v1Lane + (uint32_t)j * 32);
            mma_bf16(oc0, pa, vr);
            mma_bf16(oc1, pa, vr + 2);
            mma_bf16(oc2, pa, v1r);
        }

        float rs0 = __shfl_sync(0xffffffffu, oc2[0], lane & ~3);
        float rs1 = __shfl_sync(0xffffffffu, oc2[2], lane & ~3);
        float i0 = 1.f / rs0;
        float i1 = 1.f / rs1;

        int r0 = m0 + gid;
        int r1 = m0 + gid + 8;
        if (r0 < NN) {
            __nv_bfloat16* op = g_attb + (size_t)(row0 + r0) * D_DIM + hoff;
            *(uint32_t*)(op + 2 * tig)     = packbf(oc0[0] * i0, oc0[1] * i0);
            *(uint32_t*)(op + 8 + 2 * tig) = packbf(oc1[0] * i0, oc1[1] * i0);
        }
        if (r1 < NN) {
            __nv_bfloat16* op = g_attb + (size_t)(row0 + r1) * D_DIM + hoff;
            *(uint32_t*)(op + 2 * tig)     = packbf(oc0[2] * i1, oc0[3] * i1);
            *(uint32_t*)(op + 8 + 2 * tig) = packbf(oc1[2] * i1, oc1[3] * i1);
        }
    }
}

// ---------------------------------------------------------------------------
// Kernel 3: h = LN1(x + att @ Wo + bo). Resident operands, 4 B slots.
// ---------------------------------------------------------------------------
__global__ void __launch_bounds__(256) k_projo_ln1(const float* __restrict__ x,
                                                   const float* __restrict__ bo,
                                                   const float* __restrict__ g1, const float* __restrict__ b1) {
    extern __shared__ char sm[];
    float* smf = (float*)sm;
    const uint32_t smB = (uint32_t)__cvta_generic_to_shared(sm);
    const uint32_t aTile = smB;
    const uint32_t bBase = smB + ATILE_BYTES;
    const int row0 = blockIdx.x << 7;

    const int tid  = threadIdx.x;
    const int warp = tid >> 5;
    const int lane = tid & 31;
    const int wm   = warp >> 2;
    const int wn   = warp & 3;

    fill_A_tile(aTile, g_attb, D_DIM, row0, 0);
    #pragma unroll
    for (int s = 0; s < 4; s++)
        fill_Bchunk(bBase + s * B_SLOT, g_Wob, D_DIM, 0, s << 5);
    cp_commit();
    cp_wait<0>();
    __syncthreads();

    float acc[4][4][4];
    zero_acc(acc);
    #pragma unroll
    for (int ch = 0; ch < 4; ch++)
        mma_chunk(aTile, bBase + ch * B_SLOT, ch, acc, wm, wn, lane);

    __syncthreads();           // all reads of A/B done before C aliases smem
    stage_c(smf, acc);

    if (tid < 128) {
        int row = row0 + tid;
        if (row < R_TOTAL) {
            const float* Cr = smf + tid * CS_STRIDE;
            const float* xr = x + (size_t)row * D_DIM;
            float s1 = 0.f, s2 = 0.f;
            #pragma unroll
            for (int c = 0; c < 128; c++) {
                float v = Cr[c] + bo[c] + xr[c];
                s1 += v; s2 += v * v;
            }
            float mean = s1 * (1.f / 128.f);
            float var  = s2 * (1.f / 128.f) - mean * mean;
            float rstd = rsqrtf(var + 1e-5f);
            float* hr = g_h + (size_t)row * D_DIM;
            uint32_t* hb = (uint32_t*)(g_hb + (size_t)row * D_DIM);
            #pragma unroll
            for (int c = 0; c < 128; c += 4) {
                float4 o;
                o.x = (Cr[c]     + bo[c]     + xr[c]     - mean) * rstd * g1[c]     + b1[c];
                o.y = (Cr[c + 1] + bo[c + 1] + xr[c + 1] - mean) * rstd * g1[c + 1] + b1[c + 1];
                o.z = (Cr[c + 2] + bo[c + 2] + xr[c + 2] - mean) * rstd * g1[c + 2] + b1[c + 2];
                o.w = (Cr[c + 3] + bo[c + 3] + xr[c + 3] - mean) * rstd * g1[c + 3] + b1[c + 3];
                *(float4*)(hr + c) = o;
                hb[c >> 1]       = packbf(o.x, o.y);
                hb[(c >> 1) + 1] = packbf(o.z, o.w);
            }
        }
    }
}

// ---------------------------------------------------------------------------
// Kernel 4: mid = gelu(h @ W1 + b1). Resident A + 8 B slots (2 N-halves).
// ---------------------------------------------------------------------------
__global__ void __launch_bounds__(256) k_ffn1(const float* __restrict__ b1) {
    extern __shared__ char sm[];
    const uint32_t smB = (uint32_t)__cvta_generic_to_shared(sm);
    const uint32_t aTile = smB;
    const uint32_t bBase = smB + ATILE_BYTES;
    const int row0 = blockIdx.x << 7;

    const int tid  = threadIdx.x;
    const int warp = tid >> 5;
    const int lane = tid & 31;
    const int gid  = lane >> 2;
    const int tig  = lane & 3;
    const int wm   = warp >> 2;
    const int wn   = warp & 3;

    fill_A_tile(aTile, g_hb, D_DIM, row0, 0);
    #pragma unroll
    for (int s = 0; s < 8; s++)
        fill_Bchunk(bBase + s * B_SLOT, g_W1b, F_DIM, (s >> 2) << 7, (s & 3) << 5);
    cp_commit();
    cp_wait<0>();
    __syncthreads();

    float acc[4][4][4];
    #pragma unroll
    for (int w = 0; w < 2; w++) {
        zero_acc(acc);
        #pragma unroll
        for (int ch = 0; ch < 4; ch++)
            mma_chunk(aTile, bBase + (w * 4 + ch) * B_SLOT, ch, acc, wm, wn, lane);

        const int col0 = w << 7;
        #pragma unroll
        for (int mt = 0; mt < 4; mt++) {
            int r0 = row0 + wm * 64 + mt * 16 + gid;
            int r1 = r0 + 8;
            #pragma unroll
            for (int nt = 0; nt < 4; nt++) {
                int col = col0 + wn * 32 + nt * 8 + (tig << 1);
                float b0 = b1[col], bb1 = b1[col + 1];
                float v0 = acc[mt][nt][0] + b0;
                float v1 = acc[mt][nt][1] + bb1;
                float v2 = acc[mt][nt][2] + b0;
                float v3 = acc[mt][nt][3] + bb1;
                float e0 = 0.5f * v0 * (1.f + erff(v0 * 0.70710678118654752f));
                float e1 = 0.5f * v1 * (1.f + erff(v1 * 0.70710678118654752f));
                float e2 = 0.5f * v2 * (1.f + erff(v2 * 0.70710678118654752f));
                float e3 = 0.5f * v3 * (1.f + erff(v3 * 0.70710678118654752f));
                if (r0 < R_TOTAL)
                    *(uint32_t*)(g_midb + (size_t)r0 * F_DIM + col) = packbf(e0, e1);
                if (r1 < R_TOTAL)
                    *(uint32_t*)(g_midb + (size_t)r1 * F_DIM + col) = packbf(e2, e3);
            }
        }
    }
}

// ---------------------------------------------------------------------------
// Kernel 5: out = LN2(h + mid @ W2 + b2). Two resident A halves + 8 B slots.
// ---------------------------------------------------------------------------
__global__ void __launch_bounds__(256) k_ffn2_ln2(const float* __restrict__ b2,
                                                  const float* __restrict__ g2,
                                                  const float* __restrict__ bt2,
                                                  float* __restrict__ out) {
    extern __shared__ char sm[];
    float* smf = (float*)sm;
    const uint32_t smB = (uint32_t)__cvta_generic_to_shared(sm);
    const uint32_t aTile = smB;                       // two halves, 2*ATILE_BYTES
    const uint32_t bBase = smB + 2 * ATILE_BYTES;
    const int row0 = blockIdx.x << 7;

    const int tid  = threadIdx.x;
    const int warp = tid >> 5;
    const int lane = tid & 31;
    const int wm   = warp >> 2;
    const int wn   = warp & 3;

    fill_A_tile(aTile,               g_midb, F_DIM, row0, 0);
    fill_A_tile(aTile + ATILE_BYTES, g_midb, F_DIM, row0, 128);
    #pragma unroll
    for (int s = 0; s < 8; s++)
        fill_Bchunk(bBase + s * B_SLOT, g_W2b, D_DIM, 0, s << 5);
    cp_commit();
    cp_wait<0>();
    __syncthreads();

    float acc[4][4][4];
    zero_acc(acc);
    #pragma unroll
    for (int ch = 0; ch < 8; ch++)
        mma_chunk(aTile + (ch >> 2) * ATILE_BYTES, bBase + ch * B_SLOT, ch & 3,
                  acc, wm, wn, lane);

    __syncthreads();
    stage_c(smf, acc);

    if (tid < 128) {
        int row = row0 + tid;
        if (row < R_TOTAL) {
            const float* Cr = smf + tid * CS_STRIDE;
            const float* hr = g_h + (size_t)row * D_DIM;
            float s1 = 0.f, s2 = 0.f;
            #pragma unroll
            for (int c = 0; c < 128; c++) {
                float v = Cr[c] + b2[c] + hr[c];
                s1 += v; s2 += v * v;
            }
            float mean = s1 * (1.f / 128.f);
            float var  = s2 * (1.f / 128.f) - mean * mean;
            float rstd = rsqrtf(var + 1e-5f);
            float* orow = out + (size_t)row * D_DIM;
            #pragma unroll
            for (int c = 0; c < 128; c += 4) {
                float4 o;
                o.x = (Cr[c]     + b2[c]     + hr[c]     - mean) * rstd * g2[c]     + bt2[c];
                o.y = (Cr[c + 1] + b2[c + 1] + hr[c + 1] - mean) * rstd * g2[c + 1] + bt2[c + 1];
                o.z = (Cr[c + 2] + b2[c + 2] + hr[c + 2] - mean) * rstd * g2[c + 2] + bt2[c + 2];
                o.w = (Cr[c + 3] + b2[c + 3] + hr[c + 3] - mean) * rstd * g2[c + 3] + bt2[c + 3];
                *(float4*)(orow + c) = o;
            }
        }
    }
}

// ---------------------------------------------------------------------------
extern "C" void kernel_launch(void* const* d_in, const int* in_sizes, int n_in,
                              void* d_out, int out_size) {
    const float* x     = (const float*)d_in[0];
    const float* Wq    = (const float*)d_in[1];
    const float* bq    = (const float*)d_in[2];
    const float* Wk    = (const float*)d_in[3];
    const float* bk    = (const float*)d_in[4];
    const float* Wv    = (const float*)d_in[5];
    const float* bv    = (const float*)d_in[6];
    const float* Wo    = (const float*)d_in[7];
    const float* bo    = (const float*)d_in[8];
    const float* ln1_g = (const float*)d_in[9];
    const float* ln1_b = (const float*)d_in[10];
    const float* W1    = (const float*)d_in[11];
    const float* b1    = (const float*)d_in[12];
    const float* W2    = (const float*)d_in[13];
    const float* b2    = (const float*)d_in[14];
    const float* ln2_g = (const float*)d_in[15];
    const float* ln2_b = (const float*)d_in[16];
    float* out = (float*)d_out;

    cudaFuncSetAttribute(k_qkv,       cudaFuncAttributeMaxDynamicSharedMemorySize, QKV_SMEM);
    cudaFuncSetAttribute(k_ffn1,      cudaFuncAttributeMaxDynamicSharedMemorySize, FFN1_SMEM);
    cudaFuncSetAttribute(k_projo_ln1, cudaFuncAttributeMaxDynamicSharedMemorySize, PROJO_SMEM);
    cudaFuncSetAttribute(k_ffn2_ln2,  cudaFuncAttributeMaxDynamicSharedMemorySize, FFN2_SMEM);

    k_cvt_w<<<64, 512>>>(Wq, Wk, Wv, Wo, W1, W2);
    k_cvt_x<<<1024, 512>>>(x);
    k_qkv<<<M_TILES, 256, QKV_SMEM>>>(bq, bk, bv);
    attn_kernel<<<NB * H_HEADS * TT, 256>>>();
    k_projo_ln1<<<M_TILES, 256, PROJO_SMEM>>>(x, bo, ln1_g, ln1_b);
    k_ffn1<<<M_TILES, 256, FFN1_SMEM>>>(b1);
    k_ffn2_ln2<<<M_TILES, 256, FFN2_SMEM>>>(b2, ln2_g, ln2_b, out);
}

// round 11
// speedup vs baseline: 1.1129x; 1.0918x over previous
#include <cuda_runtime.h>
#include <cuda_bf16.h>
#include <math.h>
#include <stdint.h>

// Problem constants
#define NB 16
#define TT 12
#define NN 325
#define D_DIM 128
#define F_DIM 256
#define H_HEADS 8
#define HD 16
#define R_TOTAL (NB*TT*NN)   // 62400
#define M_TILES ((R_TOTAL + 127) / 128)   // 488

// Attention padding
#define NKP 336
#define VT_STRIDE 344

// log2(e)/4 folded into q so attention uses plain exp2
#define QSCALE 0.36067376022224085f

// ---------------------------------------------------------------------------
// Scratch (device globals: allocation-guard safe)
// ---------------------------------------------------------------------------
__device__ __nv_bfloat16 g_qb [R_TOTAL * D_DIM];   // pre-scaled by QSCALE
__device__ __nv_bfloat16 g_kb [R_TOTAL * D_DIM];
__device__ __nv_bfloat16 g_vb [R_TOTAL * D_DIM];
__device__ __nv_bfloat16 g_attb[R_TOTAL * D_DIM];
__device__ float         g_h  [R_TOTAL * D_DIM];   // fp32 LN1 output (residual + GEMM src)
__device__ __nv_bfloat16 g_Wqb[D_DIM * D_DIM];
__device__ __nv_bfloat16 g_Wkb[D_DIM * D_DIM];
__device__ __nv_bfloat16 g_Wvb[D_DIM * D_DIM];
__device__ __nv_bfloat16 g_Wob[D_DIM * D_DIM];
__device__ __nv_bfloat16 g_W1b[D_DIM * F_DIM];
__device__ __nv_bfloat16 g_W2b[F_DIM * D_DIM];

// ---------------------------------------------------------------------------
// Common helpers
// ---------------------------------------------------------------------------
__device__ __forceinline__ uint32_t packbf(float x, float y) {  // lo=x, hi=y
    uint32_t r;
    asm("cvt.rn.bf16x2.f32 %0, %1, %2;" : "=r"(r) : "f"(y), "f"(x));
    return r;
}

__device__ __forceinline__ float ex2(float x) {
    float r;
    asm("ex2.approx.f32 %0, %1;" : "=f"(r) : "f"(x));
    return r;
}

__device__ __forceinline__ void mma_bf16(float c[4], const uint32_t a[4], const uint32_t b[2]) {
    asm volatile(
        "mma.sync.aligned.m16n8k16.row.col.f32.bf16.bf16.f32 "
        "{%0,%1,%2,%3}, {%4,%5,%6,%7}, {%8,%9}, {%0,%1,%2,%3};"
        : "+f"(c[0]), "+f"(c[1]), "+f"(c[2]), "+f"(c[3])
        : "r"(a[0]), "r"(a[1]), "r"(a[2]), "r"(a[3]), "r"(b[0]), "r"(b[1]));
}

__device__ __forceinline__ void ldsm_x4(uint32_t r[4], uint32_t addr) {
    asm volatile("ldmatrix.sync.aligned.m8n8.x4.shared.b16 {%0,%1,%2,%3}, [%4];"
        : "=r"(r[0]), "=r"(r[1]), "=r"(r[2]), "=r"(r[3]) : "r"(addr));
}
__device__ __forceinline__ void ldsm_x2(uint32_t r[2], uint32_t addr) {
    asm volatile("ldmatrix.sync.aligned.m8n8.x2.shared.b16 {%0,%1}, [%2];"
        : "=r"(r[0]), "=r"(r[1]) : "r"(addr));
}
__device__ __forceinline__ void ldsm_x2t(uint32_t r[2], uint32_t addr) {
    asm volatile("ldmatrix.sync.aligned.m8n8.x2.trans.shared.b16 {%0,%1}, [%2];"
        : "=r"(r[0]), "=r"(r[1]) : "r"(addr));
}

__device__ __forceinline__ void cp16(uint32_t smaddr, const void* gaddr) {
    asm volatile("cp.async.cg.shared.global [%0], [%1], 16;" :: "r"(smaddr), "l"(gaddr));
}
__device__ __forceinline__ void cp_commit() {
    asm volatile("cp.async.commit_group;");
}
template <int N>
__device__ __forceinline__ void cp_wait() {
    asm volatile("cp.async.wait_group %0;" :: "n"(N));
}

// ---------------------------------------------------------------------------
// GEMM geometry: CTA 128x128 out tile, 8 warps (2x4), warp 64x32,
// resident operands, barrier-free MMA streams.
// ---------------------------------------------------------------------------
#define BS_U32 68
#define B_SLOT (32 * BS_U32 * 4)            // 8704 bytes per 32-k B chunk
#define ATILE_STRIDE 272                    // 128 bf16 + 16B pad
#define ATILE_BYTES (128 * ATILE_STRIDE)    // 34816
#define MID_STRIDE 528                      // 256 bf16 + 16B pad
#define MID_BYTES (128 * MID_STRIDE)        // 67584
#define CS_STRIDE 130
#define C_BYTES (128 * CS_STRIDE * 4)       // 66560

#define QKV_SMEM  (ATILE_BYTES + 12 * B_SLOT)             // 139264
#define PROJO_SMEM (ATILE_BYTES + 4 * B_SLOT)             // 69632 (>= C_BYTES)
#define FFNF_SMEM (ATILE_BYTES + 16 * B_SLOT)             // 174080

// Fill bf16 A tile by converting fp32 source rows (LDG float4 -> STS 8B).
__device__ __forceinline__ void fill_A_from_f32(char* sm, uint32_t aTileOff,
                                                const float* __restrict__ A,
                                                int lda, int row0) {
    const int tid = threadIdx.x;
    #pragma unroll
    for (int it = 0; it < 16; it++) {
        int idx = tid + it * 256;
        int r = idx >> 5, c4 = (idx & 31) << 2;
        int row = row0 + r;
        if (row > R_TOTAL - 1) row = R_TOTAL - 1;
        float4 v = *(const float4*)(A + (size_t)row * lda + c4);
        uint32_t* p = (uint32_t*)(sm + aTileOff + r * ATILE_STRIDE + c4 * 2);
        p[0] = packbf(v.x, v.y);
        p[1] = packbf(v.z, v.w);
    }
}

// Fill bf16 A tile from bf16 source via cp.async (no commit).
__device__ __forceinline__ void fill_A_bf16(uint32_t aTile,
                                            const __nv_bfloat16* __restrict__ A,
                                            int lda, int row0) {
    const int tid = threadIdx.x;
    #pragma unroll
    for (int it = 0; it < 8; it++) {
        int idx = tid + it * 256;
        int r = idx >> 4, seg = idx & 15;
        int row = row0 + r;
        if (row > R_TOTAL - 1) row = R_TOTAL - 1;
        cp16(aTile + r * ATILE_STRIDE + seg * 16,
             A + (size_t)row * lda + seg * 8);
    }
}

// Fill one 32-k B chunk (no commit)
__device__ __forceinline__ void fill_Bchunk(uint32_t dst,
                                            const __nv_bfloat16* __restrict__ B, int ldb,
                                            int bcol0, int kofs) {
    const int tid = threadIdx.x;
    #pragma unroll
    for (int it = 0; it < 2; it++) {
        int idx = tid + it * 256;
        int k = idx >> 4, seg = idx & 15;
        cp16(dst + k * (BS_U32 * 4) + seg * 16,
             B + (size_t)(kofs + k) * ldb + bcol0 + seg * 8);
    }
}

// One 32-k chunk of MMAs; A tile row stride parameterized.
__device__ __forceinline__ void mma_chunk(uint32_t aTile, uint32_t aStride,
                                          uint32_t bSlot, int ch,
                                          float acc[4][4][4], int wm, int wn, int lane) {
    const uint32_t aBase = aTile + (uint32_t)(wm * 64 + (lane & 15)) * aStride
                         + (uint32_t)(ch * 64) + ((uint32_t)(lane >> 4) << 4);
    const uint32_t bBase = bSlot + (uint32_t)(lane & 15) * (BS_U32 * 4) + (uint32_t)wn * 64;
    #pragma unroll
    for (int ks = 0; ks < 2; ks++) {
        uint32_t af[4][4], bfr[4][2];
        #pragma unroll
        for (int mt = 0; mt < 4; mt++)
            ldsm_x4(af[mt], aBase + mt * (16 * aStride) + ks * 32);
        #pragma unroll
        for (int nt = 0; nt < 4; nt++)
            ldsm_x2t(bfr[nt], bBase + ks * (16 * BS_U32 * 4) + nt * 16);
        #pragma unroll
        for (int mt = 0; mt < 4; mt++)
            #pragma unroll
            for (int nt = 0; nt < 4; nt++)
                mma_bf16(acc[mt][nt], af[mt], bfr[nt]);
    }
}

__device__ __forceinline__ void zero_acc(float acc[4][4][4]) {
    #pragma unroll
    for (int i = 0; i < 4; i++)
        #pragma unroll
        for (int j = 0; j < 4; j++)
            #pragma unroll
            for (int r = 0; r < 4; r++) acc[i][j][r] = 0.f;
}

// Stage accumulators to smem C[128][130] for row-wise epilogues.
__device__ __forceinline__ void stage_c(float* smf, float acc[4][4][4]) {
    const int tid  = threadIdx.x;
    const int warp = tid >> 5;
    const int lane = tid & 31;
    const int gid  = lane >> 2;
    const int tig  = lane & 3;
    const int wm   = warp >> 2;
    const int wn   = warp & 3;
    #pragma unroll
    for (int mt = 0; mt < 4; mt++) {
        #pragma unroll
        for (int nt = 0; nt < 4; nt++) {
            int row = wm * 64 + mt * 16 + gid;
            int col = wn * 32 + nt * 8 + (tig << 1);
            *(float2*)(smf + row * CS_STRIDE + col)       = make_float2(acc[mt][nt][0], acc[mt][nt][1]);
            *(float2*)(smf + (row + 8) * CS_STRIDE + col) = make_float2(acc[mt][nt][2], acc[mt][nt][3]);
        }
    }
    __syncthreads();
}

// ---------------------------------------------------------------------------
// Weight conversion (fp32 -> bf16); tiny.
// ---------------------------------------------------------------------------
__global__ void k_cvt_w(const float* __restrict__ Wq, const float* __restrict__ Wk,
                        const float* __restrict__ Wv, const float* __restrict__ Wo,
                        const float* __restrict__ W1, const float* __restrict__ W2) {
    const int n4 = (4 * 16384 + 2 * 32768) / 4;   // 32768
    for (int i = blockIdx.x * blockDim.x + threadIdx.x; i < n4; i += gridDim.x * blockDim.x) {
        const float* src;
        __nv_bfloat16* dst;
        int off;
        if      (i < 4096)  { src = Wq; dst = g_Wqb; off = i; }
        else if (i < 8192)  { src = Wk; dst = g_Wkb; off = i - 4096; }
        else if (i < 12288) { src = Wv; dst = g_Wvb; off = i - 8192; }
        else if (i < 16384) { src = Wo; dst = g_Wob; off = i - 12288; }
        else if (i < 24576) { src = W1; dst = g_W1b; off = i - 16384; }
        else                { src = W2; dst = g_W2b; off = i - 24576; }
        float4 v = *(const float4*)(src + (size_t)off * 4);
        uint32_t* d = (uint32_t*)dst + off * 2;
        d[0] = packbf(v.x, v.y);
        d[1] = packbf(v.z, v.w);
    }
}

// ---------------------------------------------------------------------------
// Kernel 1: QKV — A converted in-kernel from fp32 x; 3 weights resident.
// ---------------------------------------------------------------------------
__global__ void __launch_bounds__(256) k_qkv(const float* __restrict__ x,
                                             const float* __restrict__ bq,
                                             const float* __restrict__ bk,
                                             const float* __restrict__ bv) {
    extern __shared__ char sm[];
    const uint32_t smB = (uint32_t)__cvta_generic_to_shared(sm);
    const uint32_t aTile = smB;
    const uint32_t bBase = smB + ATILE_BYTES;
    const int row0 = blockIdx.x << 7;

    const int tid  = threadIdx.x;
    const int warp = tid >> 5;
    const int lane = tid & 31;
    const int gid  = lane >> 2;
    const int tig  = lane & 3;
    const int wm   = warp >> 2;
    const int wn   = warp & 3;

    #pragma unroll
    for (int s = 0; s < 12; s++) {
        const __nv_bfloat16* W = (s < 4) ? g_Wqb : (s < 8) ? g_Wkb : g_Wvb;
        fill_Bchunk(bBase + s * B_SLOT, W, D_DIM, 0, (s & 3) << 5);
    }
    cp_commit();
    fill_A_from_f32(sm, 0, x, D_DIM, row0);
    cp_wait<0>();
    __syncthreads();

    float acc[4][4][4];
    #pragma unroll
    for (int w = 0; w < 3; w++) {
        zero_acc(acc);
        #pragma unroll
        for (int ch = 0; ch < 4; ch++)
            mma_chunk(aTile, ATILE_STRIDE, bBase + (w * 4 + ch) * B_SLOT, ch, acc, wm, wn, lane);

        const float* bias   = (w == 0) ? bq : (w == 1) ? bk : bv;
        __nv_bfloat16* out  = (w == 0) ? g_qb : (w == 1) ? g_kb : g_vb;
        const float scale   = (w == 0) ? QSCALE : 1.f;
        #pragma unroll
        for (int mt = 0; mt < 4; mt++) {
            int r0 = row0 + wm * 64 + mt * 16 + gid;
            int r1 = r0 + 8;
            #pragma unroll
            for (int nt = 0; nt < 4; nt++) {
                int col = wn * 32 + nt * 8 + (tig << 1);
                float b0 = bias[col], b1 = bias[col + 1];
                if (r0 < R_TOTAL)
                    *(uint32_t*)(out + (size_t)r0 * D_DIM + col) =
                        packbf((acc[mt][nt][0] + b0) * scale, (acc[mt][nt][1] + b1) * scale);
                if (r1 < R_TOTAL)
                    *(uint32_t*)(out + (size_t)r1 * D_DIM + col) =
                        packbf((acc[mt][nt][2] + b0) * scale, (acc[mt][nt][3] + b1) * scale);
            }
        }
    }
}

// ---------------------------------------------------------------------------
// Kernel 2: attention per (b,h,t). grid = 1536, block = 256. (proven R8 form)
// ---------------------------------------------------------------------------
__global__ void __launch_bounds__(256) attn_kernel() {
    __shared__ __align__(16) uint32_t Qs[NKP * 8];
    __shared__ __align__(16) uint32_t Ks[NKP * 12];
    __shared__ __align__(16) uint32_t Vt[24 * (VT_STRIDE / 2)];

    const int bid = blockIdx.x;
    const int t = bid % TT;
    const int h = (bid / TT) % H_HEADS;
    const int b = bid / (TT * H_HEADS);
    const int row0 = (b * TT + t) * NN;
    const int hoff = h * HD;
    const int tid = threadIdx.x;

    __nv_bfloat16* Vtb = (__nv_bfloat16*)Vt;

    for (int idx = tid; idx < NKP * 2; idx += 256) {
        int m = idx >> 1;
        int seg = idx & 1;
        uint4 qv, kv, vv;
        if (m < NN) {
            size_t base = (size_t)(row0 + m) * D_DIM + hoff + seg * 8;
            qv = *(const uint4*)(g_qb + base);
            kv = *(const uint4*)(g_kb + base);
            vv = *(const uint4*)(g_vb + base);
        } else {
            qv = kv = vv = make_uint4(0, 0, 0, 0);
        }
        *(uint4*)(Qs + m * 8 + seg * 4) = qv;
        *(uint4*)(Ks + m * 12 + seg * 4) = kv;
        int d0 = seg * 8;
        uint32_t vu[4] = {vv.x, vv.y, vv.z, vv.w};
        #pragma unroll
        for (int j = 0; j < 4; j++) {
            __nv_bfloat162 p = *(__nv_bfloat162*)&vu[j];
            Vtb[(d0 + 2 * j)     * VT_STRIDE + m] = p.x;
            Vtb[(d0 + 2 * j + 1) * VT_STRIDE + m] = p.y;
        }
    }
    for (int i = tid; i < 8 * (VT_STRIDE / 2); i += 256) {
        int r = 16 + i / (VT_STRIDE / 2);
        int cu = i % (VT_STRIDE / 2);
        int m = cu * 2;
        uint32_t val = 0;
        if (r == 16) {
            if (m + 1 < NN)      val = 0x3F803F80u;
            else if (m < NN)     val = 0x00003F80u;
        }
        Vt[r * (VT_STRIDE / 2) + cu] = val;
    }
    __syncthreads();

    const int warp = tid >> 5;
    const int lane = tid & 31;
    const int gid  = lane >> 2;
    const int tig  = lane & 3;

    const int rowInTile = (lane & 7) + ((lane >> 4) << 3);
    const uint32_t off16 = (uint32_t)(lane & 8) << 1;
    const uint32_t ksSm = (uint32_t)__cvta_generic_to_shared(Ks);
    const uint32_t vtSm = (uint32_t)__cvta_generic_to_shared(Vt);
    const uint32_t kLane  = ksSm + (uint32_t)rowInTile * 48 + off16;
    const uint32_t vLane  = vtSm + (uint32_t)rowInTile * (VT_STRIDE * 2) + off16;
    const uint32_t v1Lane = vtSm + (uint32_t)(16 + (lane & 7)) * (VT_STRIDE * 2) + off16;

    for (int mt = warp; mt < 21; mt += 8) {
        const int m0 = mt << 4;
        uint32_t qa[4];
        qa[0] = Qs[(m0 + gid) * 8 + tig];
        qa[1] = Qs[(m0 + gid + 8) * 8 + tig];
        qa[2] = Qs[(m0 + gid) * 8 + tig + 4];
        qa[3] = Qs[(m0 + gid + 8) * 8 + tig + 4];

        float oc0[4] = {0.f, 0.f, 0.f, 0.f};
        float oc1[4] = {0.f, 0.f, 0.f, 0.f};
        float oc2[4] = {0.f, 0.f, 0.f, 0.f};

        for (int j = 0; j < 21; j++) {
            float c0[4] = {0.f, 0.f, 0.f, 0.f};
            float c1[4] = {0.f, 0.f, 0.f, 0.f};
            uint32_t kr[4];
            ldsm_x4(kr, kLane + (uint32_t)j * (16 * 48));
            mma_bf16(c0, qa, kr);
            mma_bf16(c1, qa, kr + 2);

            float p00 = ex2(c0[0]);
            float p01 = ex2(c0[1]);
            float p02 = ex2(c0[2]);
            float p03 = ex2(c0[3]);
            float p10 = ex2(c1[0]);
            float p11 = ex2(c1[1]);
            float p12 = ex2(c1[2]);
            float p13 = ex2(c1[3]);

            uint32_t pa[4];
            pa[0] = packbf(p00, p01);
            pa[1] = packbf(p02, p03);
            pa[2] = packbf(p10, p11);
            pa[3] = packbf(p12, p13);

            uint32_t vr[4], v1r[2];
            ldsm_x4(vr, vLane + (uint32_t)j * 32);
            ldsm_x2(v1r, v1Lane + (uint32_t)j * 32);
            mma_bf16(oc0, pa, vr);
            mma_bf16(oc1, pa, vr + 2);
            mma_bf16(oc2, pa, v1r);
        }

        float rs0 = __shfl_sync(0xffffffffu, oc2[0], lane & ~3);
        float rs1 = __shfl_sync(0xffffffffu, oc2[2], lane & ~3);
        float i0 = 1.f / rs0;
        float i1 = 1.f / rs1;

        int r0 = m0 + gid;
        int r1 = m0 + gid + 8;
        if (r0 < NN) {
            __nv_bfloat16* op = g_attb + (size_t)(row0 + r0) * D_DIM + hoff;
            *(uint32_t*)(op + 2 * tig)     = packbf(oc0[0] * i0, oc0[1] * i0);
            *(uint32_t*)(op + 8 + 2 * tig) = packbf(oc1[0] * i0, oc1[1] * i0);
        }
        if (r1 < NN) {
            __nv_bfloat16* op = g_attb + (size_t)(row0 + r1) * D_DIM + hoff;
            *(uint32_t*)(op + 2 * tig)     = packbf(oc0[2] * i1, oc0[3] * i1);
            *(uint32_t*)(op + 8 + 2 * tig) = packbf(oc1[2] * i1, oc1[3] * i1);
        }
    }
}

// ---------------------------------------------------------------------------
// Kernel 3: h = LN1(x + att @ Wo + bo). Writes fp32 g_h only.
// ---------------------------------------------------------------------------
__global__ void __launch_bounds__(256) k_projo_ln1(const float* __restrict__ x,
                                                   const float* __restrict__ bo,
                                                   const float* __restrict__ g1, const float* __restrict__ b1) {
    extern __shared__ char sm[];
    float* smf = (float*)sm;
    const uint32_t smB = (uint32_t)__cvta_generic_to_shared(sm);
    const uint32_t aTile = smB;
    const uint32_t bBase = smB + ATILE_BYTES;
    const int row0 = blockIdx.x << 7;

    const int tid  = threadIdx.x;
    const int warp = tid >> 5;
    const int lane = tid & 31;
    const int wm   = warp >> 2;
    const int wn   = warp & 3;

    fill_A_bf16(aTile, g_attb, D_DIM, row0);
    #pragma unroll
    for (int s = 0; s < 4; s++)
        fill_Bchunk(bBase + s * B_SLOT, g_Wob, D_DIM, 0, s << 5);
    cp_commit();
    cp_wait<0>();
    __syncthreads();

    float acc[4][4][4];
    zero_acc(acc);
    #pragma unroll
    for (int ch = 0; ch < 4; ch++)
        mma_chunk(aTile, ATILE_STRIDE, bBase + ch * B_SLOT, ch, acc, wm, wn, lane);

    __syncthreads();
    stage_c(smf, acc);

    if (tid < 128) {
        int row = row0 + tid;
        if (row < R_TOTAL) {
            const float* Cr = smf + tid * CS_STRIDE;
            const float* xr = x + (size_t)row * D_DIM;
            float s1 = 0.f, s2 = 0.f;
            #pragma unroll
            for (int c = 0; c < 128; c++) {
                float v = Cr[c] + bo[c] + xr[c];
                s1 += v; s2 += v * v;
            }
            float mean = s1 * (1.f / 128.f);
            float var  = s2 * (1.f / 128.f) - mean * mean;
            float rstd = rsqrtf(var + 1e-5f);
            float* hr = g_h + (size_t)row * D_DIM;
            #pragma unroll
            for (int c = 0; c < 128; c += 4) {
                float4 o;
                o.x = (Cr[c]     + bo[c]     + xr[c]     - mean) * rstd * g1[c]     + b1[c];
                o.y = (Cr[c + 1] + bo[c + 1] + xr[c + 1] - mean) * rstd * g1[c + 1] + b1[c + 1];
                o.z = (Cr[c + 2] + bo[c + 2] + xr[c + 2] - mean) * rstd * g1[c + 2] + b1[c + 2];
                o.w = (Cr[c + 3] + bo[c + 3] + xr[c + 3] - mean) * rstd * g1[c + 3] + b1[c + 3];
                *(float4*)(hr + c) = o;
            }
        }
    }
}

// ---------------------------------------------------------------------------
// Kernel 4 (FUSED): out = LN2(h + gelu(h@W1+b1)@W2 + b2).
// A-tile from fp32 h (cvt in-kernel); W1+W2 resident (16 slots); mid never
// leaves SMEM. smem = 174080 (1 CTA/SM).
// ---------------------------------------------------------------------------
__global__ void __launch_bounds__(256) k_ffn_fused(const float* __restrict__ b1,
                                                   const float* __restrict__ b2,
                                                   const float* __restrict__ g2,
                                                   const float* __restrict__ bt2,
                                                   float* __restrict__ out) {
    extern __shared__ char sm[];
    float* smf = (float*)sm;
    const uint32_t smB = (uint32_t)__cvta_generic_to_shared(sm);
    const uint32_t aTile = smB;                      // [0, 34816)
    const uint32_t w1Base = smB + ATILE_BYTES;       // [34816, 104448)
    const uint32_t w2Base = w1Base + 8 * B_SLOT;     // [104448, 174080)
    const uint32_t midTile = smB;                    // aliases A+W1 after GEMM1
    const int row0 = blockIdx.x << 7;

    const int tid  = threadIdx.x;
    const int warp = tid >> 5;
    const int lane = tid & 31;
    const int gid  = lane >> 2;
    const int tig  = lane & 3;
    const int wm   = warp >> 2;
    const int wn   = warp & 3;

    #pragma unroll
    for (int s = 0; s < 8; s++)
        fill_Bchunk(w1Base + s * B_SLOT, g_W1b, F_DIM, (s >> 2) << 7, (s & 3) << 5);
    #pragma unroll
    for (int s = 0; s < 8; s++)
        fill_Bchunk(w2Base + s * B_SLOT, g_W2b, D_DIM, 0, s << 5);
    cp_commit();
    fill_A_from_f32(sm, 0, g_h, D_DIM, row0);
    cp_wait<0>();
    __syncthreads();

    // GEMM1: both N-halves of h @ W1 kept in registers.
    float acc0[4][4][4], acc1[4][4][4];
    zero_acc(acc0);
    zero_acc(acc1);
    #pragma unroll
    for (int ch = 0; ch < 4; ch++)
        mma_chunk(aTile, ATILE_STRIDE, w1Base + ch * B_SLOT, ch, acc0, wm, wn, lane);
    #pragma unroll
    for (int ch = 0; ch < 4; ch++)
        mma_chunk(aTile, ATILE_STRIDE, w1Base + (4 + ch) * B_SLOT, ch, acc1, wm, wn, lane);

    __syncthreads();   // all reads of A-tile and W1 done; mid may now overwrite

    // gelu + bias, pack bf16, store to mid tile (stride 528B).
    __nv_bfloat16* midb = (__nv_bfloat16*)sm;   // row r at byte r*MID_STRIDE
    #pragma unroll
    for (int w = 0; w < 2; w++) {
        float (*acc)[4][4] = (w == 0) ? acc0 : acc1;
        const int col0 = w << 7;
        #pragma unroll
        for (int mt = 0; mt < 4; mt++) {
            int lr0 = wm * 64 + mt * 16 + gid;
            int lr1 = lr0 + 8;
            #pragma unroll
            for (int nt = 0; nt < 4; nt++) {
                int col = col0 + wn * 32 + nt * 8 + (tig << 1);
                float bb0 = b1[col], bb1 = b1[col + 1];
                float v0 = acc[mt][nt][0] + bb0;
                float v1 = acc[mt][nt][1] + bb1;
                float v2 = acc[mt][nt][2] + bb0;
                float v3 = acc[mt][nt][3] + bb1;
                float e0 = 0.5f * v0 * (1.f + erff(v0 * 0.70710678118654752f));
                float e1 = 0.5f * v1 * (1.f + erff(v1 * 0.70710678118654752f));
                float e2 = 0.5f * v2 * (1.f + erff(v2 * 0.70710678118654752f));
                float e3 = 0.5f * v3 * (1.f + erff(v3 * 0.70710678118654752f));
                *(uint32_t*)((char*)midb + lr0 * MID_STRIDE + col * 2) = packbf(e0, e1);
                *(uint32_t*)((char*)midb + lr1 * MID_STRIDE + col * 2) = packbf(e2, e3);
            }
        }
    }
    __syncthreads();

    // GEMM2: mid(128x256) @ W2(256x128), k = 8 chunks of 32.
    zero_acc(acc0);
    #pragma unroll
    for (int ch = 0; ch < 8; ch++)
        mma_chunk(midTile, MID_STRIDE, w2Base + ch * B_SLOT, ch, acc0, wm, wn, lane);

    __syncthreads();   // all mid reads done; C may alias
    stage_c(smf, acc0);

    if (tid < 128) {
        int row = row0 + tid;
        if (row < R_TOTAL) {
            const float* Cr = smf + tid * CS_STRIDE;
            const float* hr = g_h + (size_t)row * D_DIM;
            float s1 = 0.f, s2 = 0.f;
            #pragma unroll
            for (int c = 0; c < 128; c++) {
                float v = Cr[c] + b2[c] + hr[c];
                s1 += v; s2 += v * v;
            }
            float mean = s1 * (1.f / 128.f);
            float var  = s2 * (1.f / 128.f) - mean * mean;
            float rstd = rsqrtf(var + 1e-5f);
            float* orow = out + (size_t)row * D_DIM;
            #pragma unroll
            for (int c = 0; c < 128; c += 4) {
                float4 o;
                o.x = (Cr[c]     + b2[c]     + hr[c]     - mean) * rstd * g2[c]     + bt2[c];
                o.y = (Cr[c + 1] + b2[c + 1] + hr[c + 1] - mean) * rstd * g2[c + 1] + bt2[c + 1];
                o.z = (Cr[c + 2] + b2[c + 2] + hr[c + 2] - mean) * rstd * g2[c + 2] + bt2[c + 2];
                o.w = (Cr[c + 3] + b2[c + 3] + hr[c + 3] - mean) * rstd * g2[c + 3] + bt2[c + 3];
                *(float4*)(orow + c) = o;
            }
        }
    }
}

// ---------------------------------------------------------------------------
extern "C" void kernel_launch(void* const* d_in, const int* in_sizes, int n_in,
                              void* d_out, int out_size) {
    const float* x     = (const float*)d_in[0];
    const float* Wq    = (const float*)d_in[1];
    const float* bq    = (const float*)d_in[2];
    const float* Wk    = (const float*)d_in[3];
    const float* bk    = (const float*)d_in[4];
    const float* Wv    = (const float*)d_in[5];
    const float* bv    = (const float*)d_in[6];
    const float* Wo    = (const float*)d_in[7];
    const float* bo    = (const float*)d_in[8];
    const float* ln1_g = (const float*)d_in[9];
    const float* ln1_b = (const float*)d_in[10];
    const float* W1    = (const float*)d_in[11];
    const float* b1    = (const float*)d_in[12];
    const float* W2    = (const float*)d_in[13];
    const float* b2    = (const float*)d_in[14];
    const float* ln2_g = (const float*)d_in[15];
    const float* ln2_b = (const float*)d_in[16];
    float* out = (float*)d_out;

    cudaFuncSetAttribute(k_qkv,       cudaFuncAttributeMaxDynamicSharedMemorySize, QKV_SMEM);
    cudaFuncSetAttribute(k_projo_ln1, cudaFuncAttributeMaxDynamicSharedMemorySize, PROJO_SMEM);
    cudaFuncSetAttribute(k_ffn_fused, cudaFuncAttributeMaxDynamicSharedMemorySize, FFNF_SMEM);

    k_cvt_w<<<64, 512>>>(Wq, Wk, Wv, Wo, W1, W2);
    k_qkv<<<M_TILES, 256, QKV_SMEM>>>(x, bq, bk, bv);
    attn_kernel<<<NB * H_HEADS * TT, 256>>>();
    k_projo_ln1<<<M_TILES, 256, PROJO_SMEM>>>(x, bo, ln1_g, ln1_b);
    k_ffn_fused<<<M_TILES, 256, FFNF_SMEM>>>(b1, b2, ln2_g, ln2_b, out);
}

// round 13
// speedup vs baseline: 1.1295x; 1.0149x over previous
#include <cuda_runtime.h>
#include <cuda_bf16.h>
#include <math.h>
#include <stdint.h>

// Problem constants
#define NB 16
#define TT 12
#define NN 325
#define D_DIM 128
#define F_DIM 256
#define H_HEADS 8
#define HD 16
#define R_TOTAL (NB*TT*NN)   // 62400
#define M_TILES ((R_TOTAL + 127) / 128)   // 488

// Attention padding
#define NKP 336
#define VT_STRIDE 344

// log2(e)/4 folded into q so attention uses plain exp2
#define QSCALE 0.36067376022224085f

// ---------------------------------------------------------------------------
// Scratch (device globals: allocation-guard safe)
// ---------------------------------------------------------------------------
__device__ __nv_bfloat16 g_qb [R_TOTAL * D_DIM];   // pre-scaled by QSCALE
__device__ __nv_bfloat16 g_kb [R_TOTAL * D_DIM];
__device__ __nv_bfloat16 g_vb [R_TOTAL * D_DIM];
__device__ __nv_bfloat16 g_attb[R_TOTAL * D_DIM];
__device__ float         g_h  [R_TOTAL * D_DIM];   // fp32 LN1 output
__device__ __nv_bfloat16 g_Wqb[D_DIM * D_DIM];
__device__ __nv_bfloat16 g_Wkb[D_DIM * D_DIM];
__device__ __nv_bfloat16 g_Wvb[D_DIM * D_DIM];
__device__ __nv_bfloat16 g_Wob[D_DIM * D_DIM];
__device__ __nv_bfloat16 g_W1b[D_DIM * F_DIM];
__device__ __nv_bfloat16 g_W2b[F_DIM * D_DIM];

// ---------------------------------------------------------------------------
// Common helpers
// ---------------------------------------------------------------------------
__device__ __forceinline__ uint32_t packbf(float x, float y) {  // lo=x, hi=y
    uint32_t r;
    asm("cvt.rn.bf16x2.f32 %0, %1, %2;" : "=r"(r) : "f"(y), "f"(x));
    return r;
}

__device__ __forceinline__ float ex2(float x) {
    float r;
    asm("ex2.approx.f32 %0, %1;" : "=f"(r) : "f"(x));
    return r;
}

__device__ __forceinline__ void mma_bf16(float c[4], const uint32_t a[4], const uint32_t b[2]) {
    asm volatile(
        "mma.sync.aligned.m16n8k16.row.col.f32.bf16.bf16.f32 "
        "{%0,%1,%2,%3}, {%4,%5,%6,%7}, {%8,%9}, {%0,%1,%2,%3};"
        : "+f"(c[0]), "+f"(c[1]), "+f"(c[2]), "+f"(c[3])
        : "r"(a[0]), "r"(a[1]), "r"(a[2]), "r"(a[3]), "r"(b[0]), "r"(b[1]));
}

__device__ __forceinline__ void ldsm_x4(uint32_t r[4], uint32_t addr) {
    asm volatile("ldmatrix.sync.aligned.m8n8.x4.shared.b16 {%0,%1,%2,%3}, [%4];"
        : "=r"(r[0]), "=r"(r[1]), "=r"(r[2]), "=r"(r[3]) : "r"(addr));
}
__device__ __forceinline__ void ldsm_x2(uint32_t r[2], uint32_t addr) {
    asm volatile("ldmatrix.sync.aligned.m8n8.x2.shared.b16 {%0,%1}, [%2];"
        : "=r"(r[0]), "=r"(r[1]) : "r"(addr));
}
__device__ __forceinline__ void ldsm_x2t(uint32_t r[2], uint32_t addr) {
    asm volatile("ldmatrix.sync.aligned.m8n8.x2.trans.shared.b16 {%0,%1}, [%2];"
        : "=r"(r[0]), "=r"(r[1]) : "r"(addr));
}

__device__ __forceinline__ void cp16(uint32_t smaddr, const void* gaddr) {
    asm volatile("cp.async.cg.shared.global [%0], [%1], 16;" :: "r"(smaddr), "l"(gaddr));
}
__device__ __forceinline__ void cp_commit() {
    asm volatile("cp.async.commit_group;");
}
template <int N>
__device__ __forceinline__ void cp_wait() {
    asm volatile("cp.async.wait_group %0;" :: "n"(N));
}

// ---------------------------------------------------------------------------
// GEMM geometry: CTA 128x128 out tile, 8 warps (2x4), warp 64x32.
// ---------------------------------------------------------------------------
#define BS_U32 68
#define B_SLOT (32 * BS_U32 * 4)            // 8704
#define ATILE_STRIDE 272
#define ATILE_BYTES (128 * ATILE_STRIDE)    // 34816
#define MID_STRIDE 528
#define MID_BYTES (128 * MID_STRIDE)        // 67584
#define CS_STRIDE 130
#define C_BYTES (128 * CS_STRIDE * 4)       // 66560

#define QKV_SMEM  (ATILE_BYTES + 4 * B_SLOT)              // 69632 -> 2 CTA/SM
#define PROJO_SMEM (ATILE_BYTES + 4 * B_SLOT)             // 69632 (>= C_BYTES)
#define FFNF_SMEM (ATILE_BYTES + MID_BYTES + 8 * B_SLOT)  // 172032

// Fill bf16 A tile by converting fp32 source rows (LDG float4 -> STS 8B).
__device__ __forceinline__ void fill_A_from_f32(char* sm, uint32_t aTileOff,
                                                const float* __restrict__ A,
                                                int lda, int row0) {
    const int tid = threadIdx.x;
    #pragma unroll
    for (int it = 0; it < 16; it++) {
        int idx = tid + it * 256;
        int r = idx >> 5, c4 = (idx & 31) << 2;
        int row = row0 + r;
        if (row > R_TOTAL - 1) row = R_TOTAL - 1;
        float4 v = *(const float4*)(A + (size_t)row * lda + c4);
        uint32_t* p = (uint32_t*)(sm + aTileOff + r * ATILE_STRIDE + c4 * 2);
        p[0] = packbf(v.x, v.y);
        p[1] = packbf(v.z, v.w);
    }
}

// Fill bf16 A tile from bf16 source via cp.async (no commit).
__device__ __forceinline__ void fill_A_bf16(uint32_t aTile,
                                            const __nv_bfloat16* __restrict__ A,
                                            int lda, int row0) {
    const int tid = threadIdx.x;
    #pragma unroll
    for (int it = 0; it < 8; it++) {
        int idx = tid + it * 256;
        int r = idx >> 4, seg = idx & 15;
        int row = row0 + r;
        if (row > R_TOTAL - 1) row = R_TOTAL - 1;
        cp16(aTile + r * ATILE_STRIDE + seg * 16,
             A + (size_t)row * lda + seg * 8);
    }
}

// Fill one 32-k B chunk (no commit)
__device__ __forceinline__ void fill_Bchunk(uint32_t dst,
                                            const __nv_bfloat16* __restrict__ B, int ldb,
                                            int bcol0, int kofs) {
    const int tid = threadIdx.x;
    #pragma unroll
    for (int it = 0; it < 2; it++) {
        int idx = tid + it * 256;
        int k = idx >> 4, seg = idx & 15;
        cp16(dst + k * (BS_U32 * 4) + seg * 16,
             B + (size_t)(kofs + k) * ldb + bcol0 + seg * 8);
    }
}

// One 32-k chunk of MMAs; A tile row stride parameterized; ch selects the
// 64-byte (32-bf16) column slice of A rows.
__device__ __forceinline__ void mma_chunk(uint32_t aTile, uint32_t aStride,
                                          uint32_t bSlot, int ch,
                                          float acc[4][4][4], int wm, int wn, int lane) {
    const uint32_t aBase = aTile + (uint32_t)(wm * 64 + (lane & 15)) * aStride
                         + (uint32_t)(ch * 64) + ((uint32_t)(lane >> 4) << 4);
    const uint32_t bBase = bSlot + (uint32_t)(lane & 15) * (BS_U32 * 4) + (uint32_t)wn * 64;
    #pragma unroll
    for (int ks = 0; ks < 2; ks++) {
        uint32_t af[4][4], bfr[4][2];
        #pragma unroll
        for (int mt = 0; mt < 4; mt++)
            ldsm_x4(af[mt], aBase + mt * (16 * aStride) + ks * 32);
        #pragma unroll
        for (int nt = 0; nt < 4; nt++)
            ldsm_x2t(bfr[nt], bBase + ks * (16 * BS_U32 * 4) + nt * 16);
        #pragma unroll
        for (int mt = 0; mt < 4; mt++)
            #pragma unroll
            for (int nt = 0; nt < 4; nt++)
                mma_bf16(acc[mt][nt], af[mt], bfr[nt]);
    }
}

__device__ __forceinline__ void zero_acc(float acc[4][4][4]) {
    #pragma unroll
    for (int i = 0; i < 4; i++)
        #pragma unroll
        for (int j = 0; j < 4; j++)
            #pragma unroll
            for (int r = 0; r < 4; r++) acc[i][j][r] = 0.f;
}

// Stage accumulators to smem C[128][130].
__device__ __forceinline__ void stage_c(float* smf, float acc[4][4][4]) {
    const int tid  = threadIdx.x;
    const int warp = tid >> 5;
    const int lane = tid & 31;
    const int gid  = lane >> 2;
    const int tig  = lane & 3;
    const int wm   = warp >> 2;
    const int wn   = warp & 3;
    #pragma unroll
    for (int mt = 0; mt < 4; mt++) {
        #pragma unroll
        for (int nt = 0; nt < 4; nt++) {
            int row = wm * 64 + mt * 16 + gid;
            int col = wn * 32 + nt * 8 + (tig << 1);
            *(float2*)(smf + row * CS_STRIDE + col)       = make_float2(acc[mt][nt][0], acc[mt][nt][1]);
            *(float2*)(smf + (row + 8) * CS_STRIDE + col) = make_float2(acc[mt][nt][2], acc[mt][nt][3]);
        }
    }
    __syncthreads();
}

// ---------------------------------------------------------------------------
// Weight conversion (fp32 -> bf16)
// ---------------------------------------------------------------------------
__global__ void k_cvt_w(const float* __restrict__ Wq, const float* __restrict__ Wk,
                        const float* __restrict__ Wv, const float* __restrict__ Wo,
                        const float* __restrict__ W1, const float* __restrict__ W2) {
    const int n4 = (4 * 16384 + 2 * 32768) / 4;   // 32768
    for (int i = blockIdx.x * blockDim.x + threadIdx.x; i < n4; i += gridDim.x * blockDim.x) {
        const float* src;
        __nv_bfloat16* dst;
        int off;
        if      (i < 4096)  { src = Wq; dst = g_Wqb; off = i; }
        else if (i < 8192)  { src = Wk; dst = g_Wkb; off = i - 4096; }
        else if (i < 12288) { src = Wv; dst = g_Wvb; off = i - 8192; }
        else if (i < 16384) { src = Wo; dst = g_Wob; off = i - 12288; }
        else if (i < 24576) { src = W1; dst = g_W1b; off = i - 16384; }
        else                { src = W2; dst = g_W2b; off = i - 24576; }
        float4 v = *(const float4*)(src + (size_t)off * 4);
        uint32_t* d = (uint32_t*)dst + off * 2;
        d[0] = packbf(v.x, v.y);
        d[1] = packbf(v.z, v.w);
    }
}

// ---------------------------------------------------------------------------
// Kernel 1: QKV — grid (488, 3), one weight per CTA, 2 CTA/SM.
// ---------------------------------------------------------------------------
__global__ void __launch_bounds__(256, 2) k_qkv(const float* __restrict__ x,
                                                const float* __restrict__ bq,
                                                const float* __restrict__ bk,
                                                const float* __restrict__ bv) {
    extern __shared__ char sm[];
    const uint32_t smB = (uint32_t)__cvta_generic_to_shared(sm);
    const uint32_t aTile = smB;
    const uint32_t bBase = smB + ATILE_BYTES;
    const int row0 = blockIdx.x << 7;
    const int which = blockIdx.y;

    const __nv_bfloat16* W = (which == 0) ? g_Wqb : (which == 1) ? g_Wkb : g_Wvb;
    const float* bias      = (which == 0) ? bq : (which == 1) ? bk : bv;
    __nv_bfloat16* out     = (which == 0) ? g_qb : (which == 1) ? g_kb : g_vb;
    const float scale      = (which == 0) ? QSCALE : 1.f;

    const int tid  = threadIdx.x;
    const int warp = tid >> 5;
    const int lane = tid & 31;
    const int gid  = lane >> 2;
    const int tig  = lane & 3;
    const int wm   = warp >> 2;
    const int wn   = warp & 3;

    #pragma unroll
    for (int s = 0; s < 4; s++)
        fill_Bchunk(bBase + s * B_SLOT, W, D_DIM, 0, s << 5);
    cp_commit();
    fill_A_from_f32(sm, 0, x, D_DIM, row0);
    cp_wait<0>();
    __syncthreads();

    float acc[4][4][4];
    zero_acc(acc);
    #pragma unroll
    for (int ch = 0; ch < 4; ch++)
        mma_chunk(aTile, ATILE_STRIDE, bBase + ch * B_SLOT, ch, acc, wm, wn, lane);

    #pragma unroll
    for (int mt = 0; mt < 4; mt++) {
        int r0 = row0 + wm * 64 + mt * 16 + gid;
        int r1 = r0 + 8;
        #pragma unroll
        for (int nt = 0; nt < 4; nt++) {
            int col = wn * 32 + nt * 8 + (tig << 1);
            float b0 = bias[col], b1 = bias[col + 1];
            if (r0 < R_TOTAL)
                *(uint32_t*)(out + (size_t)r0 * D_DIM + col) =
                    packbf((acc[mt][nt][0] + b0) * scale, (acc[mt][nt][1] + b1) * scale);
            if (r1 < R_TOTAL)
                *(uint32_t*)(out + (size_t)r1 * D_DIM + col) =
                    packbf((acc[mt][nt][2] + b0) * scale, (acc[mt][nt][3] + b1) * scale);
        }
    }
}

// ---------------------------------------------------------------------------
// Kernel 2: attention per (b,h,t). grid = 1536, block = 256. (proven R8 form)
// ---------------------------------------------------------------------------
__global__ void __launch_bounds__(256) attn_kernel() {
    __shared__ __align__(16) uint32_t Qs[NKP * 8];
    __shared__ __align__(16) uint32_t Ks[NKP * 12];
    __shared__ __align__(16) uint32_t Vt[24 * (VT_STRIDE / 2)];

    const int bid = blockIdx.x;
    const int t = bid % TT;
    const int h = (bid / TT) % H_HEADS;
    const int b = bid / (TT * H_HEADS);
    const int row0 = (b * TT + t) * NN;
    const int hoff = h * HD;
    const int tid = threadIdx.x;

    __nv_bfloat16* Vtb = (__nv_bfloat16*)Vt;

    for (int idx = tid; idx < NKP * 2; idx += 256) {
        int m = idx >> 1;
        int seg = idx & 1;
        uint4 qv, kv, vv;
        if (m < NN) {
            size_t base = (size_t)(row0 + m) * D_DIM + hoff + seg * 8;
            qv = *(const uint4*)(g_qb + base);
            kv = *(const uint4*)(g_kb + base);
            vv = *(const uint4*)(g_vb + base);
        } else {
            qv = kv = vv = make_uint4(0, 0, 0, 0);
        }
        *(uint4*)(Qs + m * 8 + seg * 4) = qv;
        *(uint4*)(Ks + m * 12 + seg * 4) = kv;
        int d0 = seg * 8;
        uint32_t vu[4] = {vv.x, vv.y, vv.z, vv.w};
        #pragma unroll
        for (int j = 0; j < 4; j++) {
            __nv_bfloat162 p = *(__nv_bfloat162*)&vu[j];
            Vtb[(d0 + 2 * j)     * VT_STRIDE + m] = p.x;
            Vtb[(d0 + 2 * j + 1) * VT_STRIDE + m] = p.y;
        }
    }
    for (int i = tid; i < 8 * (VT_STRIDE / 2); i += 256) {
        int r = 16 + i / (VT_STRIDE / 2);
        int cu = i % (VT_STRIDE / 2);
        int m = cu * 2;
        uint32_t val = 0;
        if (r == 16) {
            if (m + 1 < NN)      val = 0x3F803F80u;
            else if (m < NN)     val = 0x00003F80u;
        }
        Vt[r * (VT_STRIDE / 2) + cu] = val;
    }
    __syncthreads();

    const int warp = tid >> 5;
    const int lane = tid & 31;
    const int gid  = lane >> 2;
    const int tig  = lane & 3;

    const int rowInTile = (lane & 7) + ((lane >> 4) << 3);
    const uint32_t off16 = (uint32_t)(lane & 8) << 1;
    const uint32_t ksSm = (uint32_t)__cvta_generic_to_shared(Ks);
    const uint32_t vtSm = (uint32_t)__cvta_generic_to_shared(Vt);
    const uint32_t kLane  = ksSm + (uint32_t)rowInTile * 48 + off16;
    const uint32_t vLane  = vtSm + (uint32_t)rowInTile * (VT_STRIDE * 2) + off16;
    const uint32_t v1Lane = vtSm + (uint32_t)(16 + (lane & 7)) * (VT_STRIDE * 2) + off16;

    for (int mt = warp; mt < 21; mt += 8) {
        const int m0 = mt << 4;
        uint32_t qa[4];
        qa[0] = Qs[(m0 + gid) * 8 + tig];
        qa[1] = Qs[(m0 + gid + 8) * 8 + tig];
        qa[2] = Qs[(m0 + gid) * 8 + tig + 4];
        qa[3] = Qs[(m0 + gid + 8) * 8 + tig + 4];

        float oc0[4] = {0.f, 0.f, 0.f, 0.f};
        float oc1[4] = {0.f, 0.f, 0.f, 0.f};
        float oc2[4] = {0.f, 0.f, 0.f, 0.f};

        for (int j = 0; j < 21; j++) {
            float c0[4] = {0.f, 0.f, 0.f, 0.f};
            float c1[4] = {0.f, 0.f, 0.f, 0.f};
            uint32_t kr[4];
            ldsm_x4(kr, kLane + (uint32_t)j * (16 * 48));
            mma_bf16(c0, qa, kr);
            mma_bf16(c1, qa, kr + 2);

            float p00 = ex2(c0[0]);
            float p01 = ex2(c0[1]);
            float p02 = ex2(c0[2]);
            float p03 = ex2(c0[3]);
            float p10 = ex2(c1[0]);
            float p11 = ex2(c1[1]);
            float p12 = ex2(c1[2]);
            float p13 = ex2(c1[3]);

            uint32_t pa[4];
            pa[0] = packbf(p00, p01);
            pa[1] = packbf(p02, p03);
            pa[2] = packbf(p10, p11);
            pa[3] = packbf(p12, p13);

            uint32_t vr[4], v1r[2];
            ldsm_x4(vr, vLane + (uint32_t)j * 32);
            ldsm_x2(v1r, v1Lane + (uint32_t)j * 32);
            mma_bf16(oc0, pa, vr);
            mma_bf16(oc1, pa, vr + 2);
            mma_bf16(oc2, pa, v1r);
        }

        float rs0 = __shfl_sync(0xffffffffu, oc2[0], lane & ~3);
        float rs1 = __shfl_sync(0xffffffffu, oc2[2], lane & ~3);
        float i0 = 1.f / rs0;
        float i1 = 1.f / rs1;

        int r0 = m0 + gid;
        int r1 = m0 + gid + 8;
        if (r0 < NN) {
            __nv_bfloat16* op = g_attb + (size_t)(row0 + r0) * D_DIM + hoff;
            *(uint32_t*)(op + 2 * tig)     = packbf(oc0[0] * i0, oc0[1] * i0);
            *(uint32_t*)(op + 8 + 2 * tig) = packbf(oc1[0] * i0, oc1[1] * i0);
        }
        if (r1 < NN) {
            __nv_bfloat16* op = g_attb + (size_t)(row0 + r1) * D_DIM + hoff;
            *(uint32_t*)(op + 2 * tig)     = packbf(oc0[2] * i1, oc0[3] * i1);
            *(uint32_t*)(op + 8 + 2 * tig) = packbf(oc1[2] * i1, oc1[3] * i1);
        }
    }
}

// ---------------------------------------------------------------------------
// Kernel 3: h = LN1(x + att @ Wo + bo). 2 CTA/SM, 256-thread LN epilogue.
// ---------------------------------------------------------------------------
__global__ void __launch_bounds__(256, 2) k_projo_ln1(const float* __restrict__ x,
                                                      const float* __restrict__ bo,
                                                      const float* __restrict__ g1,
                                                      const float* __restrict__ b1) {
    extern __shared__ char sm[];
    float* smf = (float*)sm;
    const uint32_t smB = (uint32_t)__cvta_generic_to_shared(sm);
    const uint32_t aTile = smB;
    const uint32_t bBase = smB + ATILE_BYTES;
    const int row0 = blockIdx.x << 7;

    const int tid  = threadIdx.x;
    const int warp = tid >> 5;
    const int lane = tid & 31;
    const int wm   = warp >> 2;
    const int wn   = warp & 3;

    fill_A_bf16(aTile, g_attb, D_DIM, row0);
    #pragma unroll
    for (int s = 0; s < 4; s++)
        fill_Bchunk(bBase + s * B_SLOT, g_Wob, D_DIM, 0, s << 5);
    cp_commit();
    cp_wait<0>();
    __syncthreads();

    float acc[4][4][4];
    zero_acc(acc);
    #pragma unroll
    for (int ch = 0; ch < 4; ch++)
        mma_chunk(aTile, ATILE_STRIDE, bBase + ch * B_SLOT, ch, acc, wm, wn, lane);

    __syncthreads();
    stage_c(smf, acc);

    // 256-thread epilogue: pair (2t, 2t+1) handles row t halves.
    {
        int lrow = tid >> 1;
        int half = tid & 1;
        int row = row0 + lrow;
        if (row < R_TOTAL) {
            const float* Cr = smf + lrow * CS_STRIDE + half * 64;
            const float* xr = x + (size_t)row * D_DIM + half * 64;
            const float* bor = bo + half * 64;
            float s1 = 0.f, s2 = 0.f;
            float vals[64];
            #pragma unroll
            for (int c = 0; c < 64; c++) {
                float v = Cr[c] + bor[c] + xr[c];
                vals[c] = v;
                s1 += v; s2 += v * v;
            }
            s1 += __shfl_xor_sync(0xffffffffu, s1, 1);
            s2 += __shfl_xor_sync(0xffffffffu, s2, 1);
            float mean = s1 * (1.f / 128.f);
            float var  = s2 * (1.f / 128.f) - mean * mean;
            float rstd = rsqrtf(var + 1e-5f);
            float* hr = g_h + (size_t)row * D_DIM + half * 64;
            const float* g1r = g1 + half * 64;
            const float* b1r = b1 + half * 64;
            #pragma unroll
            for (int c = 0; c < 64; c += 4) {
                float4 o;
                o.x = (vals[c]     - mean) * rstd * g1r[c]     + b1r[c];
                o.y = (vals[c + 1] - mean) * rstd * g1r[c + 1] + b1r[c + 1];
                o.z = (vals[c + 2] - mean) * rstd * g1r[c + 2] + b1r[c + 2];
                o.w = (vals[c + 3] - mean) * rstd * g1r[c + 3] + b1r[c + 3];
                *(float4*)(hr + c) = o;
            }
        }
    }
}

// ---------------------------------------------------------------------------
// Kernel 4 (FUSED, single-acc): out = LN2(h + gelu(h@W1+b1)@W2 + b2).
// Layout: A [0,34816), mid [34816,102400) stride 528, wbuf [102400,172032).
// W1 occupies wbuf for GEMM1, then W2 refills the same slots for GEMM2.
// ---------------------------------------------------------------------------
__global__ void __launch_bounds__(256) k_ffn_fused(const float* __restrict__ b1,
                                                   const float* __restrict__ b2,
                                                   const float* __restrict__ g2,
                                                   const float* __restrict__ bt2,
                                                   float* __restrict__ out) {
    extern __shared__ char sm[];
    float* smf = (float*)sm;
    const uint32_t smB = (uint32_t)__cvta_generic_to_shared(sm);
    const uint32_t aTile = smB;
    const uint32_t midTile = smB + ATILE_BYTES;
    const uint32_t wBase = midTile + MID_BYTES;
    const int row0 = blockIdx.x << 7;

    const int tid  = threadIdx.x;
    const int warp = tid >> 5;
    const int lane = tid & 31;
    const int gid  = lane >> 2;
    const int tig  = lane & 3;
    const int wm   = warp >> 2;
    const int wn   = warp & 3;

    #pragma unroll
    for (int s = 0; s < 8; s++)
        fill_Bchunk(wBase + s * B_SLOT, g_W1b, F_DIM, (s >> 2) << 7, (s & 3) << 5);
    cp_commit();
    fill_A_from_f32(sm, 0, g_h, D_DIM, row0);
    cp_wait<0>();
    __syncthreads();

    float acc[4][4][4];
    __nv_bfloat16* midb = (__nv_bfloat16*)(sm + ATILE_BYTES);

    // GEMM1: two N-halves sequentially with ONE acc set; mid is separate smem.
    #pragma unroll
    for (int w = 0; w < 2; w++) {
        zero_acc(acc);
        #pragma unroll
        for (int ch = 0; ch < 4; ch++)
            mma_chunk(aTile, ATILE_STRIDE, wBase + (w * 4 + ch) * B_SLOT, ch, acc, wm, wn, lane);

        const int col0 = w << 7;
        #pragma unroll
        for (int mt = 0; mt < 4; mt++) {
            int lr0 = wm * 64 + mt * 16 + gid;
            int lr1 = lr0 + 8;
            #pragma unroll
            for (int nt = 0; nt < 4; nt++) {
                int col = col0 + wn * 32 + nt * 8 + (tig << 1);
                float bb0 = b1[col], bb1 = b1[col + 1];
                float v0 = acc[mt][nt][0] + bb0;
                float v1 = acc[mt][nt][1] + bb1;
                float v2 = acc[mt][nt][2] + bb0;
                float v3 = acc[mt][nt][3] + bb1;
                float e0 = 0.5f * v0 * (1.f + erff(v0 * 0.70710678118654752f));
                float e1 = 0.5f * v1 * (1.f + erff(v1 * 0.70710678118654752f));
                float e2 = 0.5f * v2 * (1.f + erff(v2 * 0.70710678118654752f));
                float e3 = 0.5f * v3 * (1.f + erff(v3 * 0.70710678118654752f));
                *(uint32_t*)((char*)midb + lr0 * MID_STRIDE + col * 2) = packbf(e0, e1);
                *(uint32_t*)((char*)midb + lr1 * MID_STRIDE + col * 2) = packbf(e2, e3);
            }
        }
    }
    __syncthreads();   // all W1 reads + mid writes done

    // Refill wbuf with W2 (8 slots, k = 256)
    #pragma unroll
    for (int s = 0; s < 8; s++)
        fill_Bchunk(wBase + s * B_SLOT, g_W2b, D_DIM, 0, s << 5);
    cp_commit();
    cp_wait<0>();
    __syncthreads();

    // GEMM2: mid(128x256) @ W2(256x128); ch (NOT ch&3) selects mid column slice.
    zero_acc(acc);
    #pragma unroll
    for (int ch = 0; ch < 8; ch++)
        mma_chunk(midTile, MID_STRIDE, wBase + ch * B_SLOT, ch, acc, wm, wn, lane);

    __syncthreads();
    stage_c(smf, acc);

    // 256-thread LN2 epilogue (pair-split rows)
    {
        int lrow = tid >> 1;
        int half = tid & 1;
        int row = row0 + lrow;
        if (row < R_TOTAL) {
            const float* Cr = smf + lrow * CS_STRIDE + half * 64;
            const float* hr = g_h + (size_t)row * D_DIM + half * 64;
            const float* b2r = b2 + half * 64;
            float s1 = 0.f, s2 = 0.f;
            float vals[64];
            #pragma unroll
            for (int c = 0; c < 64; c++) {
                float v = Cr[c] + b2r[c] + hr[c];
                vals[c] = v;
                s1 += v; s2 += v * v;
            }
            s1 += __shfl_xor_sync(0xffffffffu, s1, 1);
            s2 += __shfl_xor_sync(0xffffffffu, s2, 1);
            float mean = s1 * (1.f / 128.f);
            float var  = s2 * (1.f / 128.f) - mean * mean;
            float rstd = rsqrtf(var + 1e-5f);
            float* orow = out + (size_t)row * D_DIM + half * 64;
            const float* g2r = g2 + half * 64;
            const float* bt2r = bt2 + half * 64;
            #pragma unroll
            for (int c = 0; c < 64; c += 4) {
                float4 o;
                o.x = (vals[c]     - mean) * rstd * g2r[c]     + bt2r[c];
                o.y = (vals[c + 1] - mean) * rstd * g2r[c + 1] + bt2r[c + 1];
                o.z = (vals[c + 2] - mean) * rstd * g2r[c + 2] + bt2r[c + 2];
                o.w = (vals[c + 3] - mean) * rstd * g2r[c + 3] + bt2r[c + 3];
                *(float4*)(orow + c) = o;
            }
        }
    }
}

// ---------------------------------------------------------------------------
extern "C" void kernel_launch(void* const* d_in, const int* in_sizes, int n_in,
                              void* d_out, int out_size) {
    const float* x     = (const float*)d_in[0];
    const float* Wq    = (const float*)d_in[1];
    const float* bq    = (const float*)d_in[2];
    const float* Wk    = (const float*)d_in[3];
    const float* bk    = (const float*)d_in[4];
    const float* Wv    = (const float*)d_in[5];
    const float* bv    = (const float*)d_in[6];
    const float* Wo    = (const float*)d_in[7];
    const float* bo    = (const float*)d_in[8];
    const float* ln1_g = (const float*)d_in[9];
    const float* ln1_b = (const float*)d_in[10];
    const float* W1    = (const float*)d_in[11];
    const float* b1    = (const float*)d_in[12];
    const float* W2    = (const float*)d_in[13];
    const float* b2    = (const float*)d_in[14];
    const float* ln2_g = (const float*)d_in[15];
    const float* ln2_b = (const float*)d_in[16];
    float* out = (float*)d_out;

    cudaFuncSetAttribute(k_qkv,       cudaFuncAttributeMaxDynamicSharedMemorySize, QKV_SMEM);
    cudaFuncSetAttribute(k_projo_ln1, cudaFuncAttributeMaxDynamicSharedMemorySize, PROJO_SMEM);
    cudaFuncSetAttribute(k_ffn_fused, cudaFuncAttributeMaxDynamicSharedMemorySize, FFNF_SMEM);

    k_cvt_w<<<64, 512>>>(Wq, Wk, Wv, Wo, W1, W2);
    k_qkv<<<dim3(M_TILES, 3), 256, QKV_SMEM>>>(x, bq, bk, bv);
    attn_kernel<<<NB * H_HEADS * TT, 256>>>();
    k_projo_ln1<<<M_TILES, 256, PROJO_SMEM>>>(x, bo, ln1_g, ln1_b);
    k_ffn_fused<<<M_TILES, 256, FFNF_SMEM>>>(b1, b2, ln2_g, ln2_b, out);
}

// round 14
// speedup vs baseline: 1.4072x; 1.2460x over previous
#include <cuda_runtime.h>
#include <cuda_bf16.h>
#include <math.h>
#include <stdint.h>

// Problem constants
#define NB 16
#define TT 12
#define NN 325
#define D_DIM 128
#define F_DIM 256
#define H_HEADS 8
#define HD 16
#define R_TOTAL (NB*TT*NN)   // 62400
#define M_TILES ((R_TOTAL + 127) / 128)   // 488

// Attention padding
#define NKP 336
#define VT_STRIDE 344

// log2(e)/4 folded into q so attention uses plain exp2
#define QSCALE 0.36067376022224085f

// ---------------------------------------------------------------------------
// Scratch (device globals: allocation-guard safe)
// ---------------------------------------------------------------------------
__device__ __nv_bfloat16 g_qb [R_TOTAL * D_DIM];   // pre-scaled by QSCALE
__device__ __nv_bfloat16 g_kb [R_TOTAL * D_DIM];
__device__ __nv_bfloat16 g_vb [R_TOTAL * D_DIM];
__device__ __nv_bfloat16 g_attb[R_TOTAL * D_DIM];
__device__ float         g_h  [R_TOTAL * D_DIM];   // fp32 LN1 output
__device__ __nv_bfloat16 g_Wqb[D_DIM * D_DIM];
__device__ __nv_bfloat16 g_Wkb[D_DIM * D_DIM];
__device__ __nv_bfloat16 g_Wvb[D_DIM * D_DIM];
__device__ __nv_bfloat16 g_Wob[D_DIM * D_DIM];
__device__ __nv_bfloat16 g_W1b[D_DIM * F_DIM];
__device__ __nv_bfloat16 g_W2b[F_DIM * D_DIM];

// ---------------------------------------------------------------------------
// Common helpers
// ---------------------------------------------------------------------------
__device__ __forceinline__ uint32_t packbf(float x, float y) {  // lo=x, hi=y
    uint32_t r;
    asm("cvt.rn.bf16x2.f32 %0, %1, %2;" : "=r"(r) : "f"(y), "f"(x));
    return r;
}

__device__ __forceinline__ float ex2(float x) {
    float r;
    asm("ex2.approx.f32 %0, %1;" : "=f"(r) : "f"(x));
    return r;
}

__device__ __forceinline__ void mma_bf16(float c[4], const uint32_t a[4], const uint32_t b[2]) {
    asm volatile(
        "mma.sync.aligned.m16n8k16.row.col.f32.bf16.bf16.f32 "
        "{%0,%1,%2,%3}, {%4,%5,%6,%7}, {%8,%9}, {%0,%1,%2,%3};"
        : "+f"(c[0]), "+f"(c[1]), "+f"(c[2]), "+f"(c[3])
        : "r"(a[0]), "r"(a[1]), "r"(a[2]), "r"(a[3]), "r"(b[0]), "r"(b[1]));
}

__device__ __forceinline__ void ldsm_x4(uint32_t r[4], uint32_t addr) {
    asm volatile("ldmatrix.sync.aligned.m8n8.x4.shared.b16 {%0,%1,%2,%3}, [%4];"
        : "=r"(r[0]), "=r"(r[1]), "=r"(r[2]), "=r"(r[3]) : "r"(addr));
}
__device__ __forceinline__ void ldsm_x2(uint32_t r[2], uint32_t addr) {
    asm volatile("ldmatrix.sync.aligned.m8n8.x2.shared.b16 {%0,%1}, [%2];"
        : "=r"(r[0]), "=r"(r[1]) : "r"(addr));
}
__device__ __forceinline__ void ldsm_x2t(uint32_t r[2], uint32_t addr) {
    asm volatile("ldmatrix.sync.aligned.m8n8.x2.trans.shared.b16 {%0,%1}, [%2];"
        : "=r"(r[0]), "=r"(r[1]) : "r"(addr));
}

__device__ __forceinline__ void cp16(uint32_t smaddr, const void* gaddr) {
    asm volatile("cp.async.cg.shared.global [%0], [%1], 16;" :: "r"(smaddr), "l"(gaddr));
}
__device__ __forceinline__ void cp_commit() {
    asm volatile("cp.async.commit_group;");
}
template <int N>
__device__ __forceinline__ void cp_wait() {
    asm volatile("cp.async.wait_group %0;" :: "n"(N));
}

// ---------------------------------------------------------------------------
// GEMM geometry: CTA 128x128 out tile, 8 warps (2x4), warp 64x32.
// ---------------------------------------------------------------------------
#define BS_U32 68
#define B_SLOT (32 * BS_U32 * 4)            // 8704
#define ATILE_STRIDE 272
#define ATILE_BYTES (128 * ATILE_STRIDE)    // 34816
#define MID_STRIDE 528
#define MID_BYTES (128 * MID_STRIDE)        // 67584
#define CS_STRIDE 132                       // 528B rows: 16B-aligned -> LDS.128
#define C_BYTES (128 * CS_STRIDE * 4)       // 67584

#define QKV_SMEM  (ATILE_BYTES + 4 * B_SLOT)              // 69632 -> 2 CTA/SM
#define PROJO_SMEM (ATILE_BYTES + 4 * B_SLOT)             // 69632 (>= C_BYTES)
#define FFNF_SMEM (ATILE_BYTES + MID_BYTES + 8 * B_SLOT)  // 172032 (>= C_BYTES)

// Fill bf16 A tile by converting fp32 source rows (LDG float4 -> STS 8B).
__device__ __forceinline__ void fill_A_from_f32(char* sm, uint32_t aTileOff,
                                                const float* __restrict__ A,
                                                int lda, int row0) {
    const int tid = threadIdx.x;
    #pragma unroll
    for (int it = 0; it < 16; it++) {
        int idx = tid + it * 256;
        int r = idx >> 5, c4 = (idx & 31) << 2;
        int row = row0 + r;
        if (row > R_TOTAL - 1) row = R_TOTAL - 1;
        float4 v = *(const float4*)(A + (size_t)row * lda + c4);
        uint32_t* p = (uint32_t*)(sm + aTileOff + r * ATILE_STRIDE + c4 * 2);
        p[0] = packbf(v.x, v.y);
        p[1] = packbf(v.z, v.w);
    }
}

// Fill bf16 A tile from bf16 source via cp.async (no commit).
__device__ __forceinline__ void fill_A_bf16(uint32_t aTile,
                                            const __nv_bfloat16* __restrict__ A,
                                            int lda, int row0) {
    const int tid = threadIdx.x;
    #pragma unroll
    for (int it = 0; it < 8; it++) {
        int idx = tid + it * 256;
        int r = idx >> 4, seg = idx & 15;
        int row = row0 + r;
        if (row > R_TOTAL - 1) row = R_TOTAL - 1;
        cp16(aTile + r * ATILE_STRIDE + seg * 16,
             A + (size_t)row * lda + seg * 8);
    }
}

// Fill one 32-k B chunk (no commit)
__device__ __forceinline__ void fill_Bchunk(uint32_t dst,
                                            const __nv_bfloat16* __restrict__ B, int ldb,
                                            int bcol0, int kofs) {
    const int tid = threadIdx.x;
    #pragma unroll
    for (int it = 0; it < 2; it++) {
        int idx = tid + it * 256;
        int k = idx >> 4, seg = idx & 15;
        cp16(dst + k * (BS_U32 * 4) + seg * 16,
             B + (size_t)(kofs + k) * ldb + bcol0 + seg * 8);
    }
}

// One 32-k chunk of MMAs; A tile row stride parameterized; ch selects the
// 64-byte (32-bf16) column slice of A rows.
__device__ __forceinline__ void mma_chunk(uint32_t aTile, uint32_t aStride,
                                          uint32_t bSlot, int ch,
                                          float acc[4][4][4], int wm, int wn, int lane) {
    const uint32_t aBase = aTile + (uint32_t)(wm * 64 + (lane & 15)) * aStride
                         + (uint32_t)(ch * 64) + ((uint32_t)(lane >> 4) << 4);
    const uint32_t bBase = bSlot + (uint32_t)(lane & 15) * (BS_U32 * 4) + (uint32_t)wn * 64;
    #pragma unroll
    for (int ks = 0; ks < 2; ks++) {
        uint32_t af[4][4], bfr[4][2];
        #pragma unroll
        for (int mt = 0; mt < 4; mt++)
            ldsm_x4(af[mt], aBase + mt * (16 * aStride) + ks * 32);
        #pragma unroll
        for (int nt = 0; nt < 4; nt++)
            ldsm_x2t(bfr[nt], bBase + ks * (16 * BS_U32 * 4) + nt * 16);
        #pragma unroll
        for (int mt = 0; mt < 4; mt++)
            #pragma unroll
            for (int nt = 0; nt < 4; nt++)
                mma_bf16(acc[mt][nt], af[mt], bfr[nt]);
    }
}

__device__ __forceinline__ void zero_acc(float acc[4][4][4]) {
    #pragma unroll
    for (int i = 0; i < 4; i++)
        #pragma unroll
        for (int j = 0; j < 4; j++)
            #pragma unroll
            for (int r = 0; r < 4; r++) acc[i][j][r] = 0.f;
}

// Stage accumulators to smem C[128][132].
__device__ __forceinline__ void stage_c(float* smf, float acc[4][4][4]) {
    const int tid  = threadIdx.x;
    const int warp = tid >> 5;
    const int lane = tid & 31;
    const int gid  = lane >> 2;
    const int tig  = lane & 3;
    const int wm   = warp >> 2;
    const int wn   = warp & 3;
    #pragma unroll
    for (int mt = 0; mt < 4; mt++) {
        #pragma unroll
        for (int nt = 0; nt < 4; nt++) {
            int row = wm * 64 + mt * 16 + gid;
            int col = wn * 32 + nt * 8 + (tig << 1);
            *(float2*)(smf + row * CS_STRIDE + col)       = make_float2(acc[mt][nt][0], acc[mt][nt][1]);
            *(float2*)(smf + (row + 8) * CS_STRIDE + col) = make_float2(acc[mt][nt][2], acc[mt][nt][3]);
        }
    }
    __syncthreads();
}

// Two-pass 256-thread LN epilogue (no per-thread buffer -> no spills).
// resid: fp32 residual source row base; out: fp32 destination.
__device__ __forceinline__ void ln_epilogue(const float* smf, int row0,
                                            const float* __restrict__ resid,
                                            const float* __restrict__ bias,
                                            const float* __restrict__ gam,
                                            const float* __restrict__ bet,
                                            float* __restrict__ out) {
    const int tid = threadIdx.x;
    int lrow = tid >> 1;
    int half = tid & 1;
    int row = row0 + lrow;
    if (row >= R_TOTAL) return;
    const float* Cr = smf + lrow * CS_STRIDE + half * 64;
    const float* rr = resid + (size_t)row * D_DIM + half * 64;
    const float* br = bias + half * 64;

    float s1 = 0.f, s2 = 0.f;
    #pragma unroll
    for (int c = 0; c < 64; c += 4) {
        float4 cv = *(const float4*)(Cr + c);
        float4 rv = *(const float4*)(rr + c);
        float4 bv = *(const float4*)(br + c);
        float v0 = cv.x + bv.x + rv.x;
        float v1 = cv.y + bv.y + rv.y;
        float v2 = cv.z + bv.z + rv.z;
        float v3 = cv.w + bv.w + rv.w;
        s1 += (v0 + v1) + (v2 + v3);
        s2 += (v0 * v0 + v1 * v1) + (v2 * v2 + v3 * v3);
    }
    s1 += __shfl_xor_sync(0xffffffffu, s1, 1);
    s2 += __shfl_xor_sync(0xffffffffu, s2, 1);
    float mean = s1 * (1.f / 128.f);
    float var  = s2 * (1.f / 128.f) - mean * mean;
    float rstd = rsqrtf(var + 1e-5f);

    float* orow = out + (size_t)row * D_DIM + half * 64;
    const float* gr = gam + half * 64;
    const float* btr = bet + half * 64;
    #pragma unroll
    for (int c = 0; c < 64; c += 4) {
        float4 cv = *(const float4*)(Cr + c);
        float4 rv = *(const float4*)(rr + c);
        float4 bv = *(const float4*)(br + c);
        float4 gv = *(const float4*)(gr + c);
        float4 bb = *(const float4*)(btr + c);
        float4 o;
        o.x = (cv.x + bv.x + rv.x - mean) * rstd * gv.x + bb.x;
        o.y = (cv.y + bv.y + rv.y - mean) * rstd * gv.y + bb.y;
        o.z = (cv.z + bv.z + rv.z - mean) * rstd * gv.z + bb.z;
        o.w = (cv.w + bv.w + rv.w - mean) * rstd * gv.w + bb.w;
        *(float4*)(orow + c) = o;
    }
}

// ---------------------------------------------------------------------------
// Weight conversion (fp32 -> bf16)
// ---------------------------------------------------------------------------
__global__ void k_cvt_w(const float* __restrict__ Wq, const float* __restrict__ Wk,
                        const float* __restrict__ Wv, const float* __restrict__ Wo,
                        const float* __restrict__ W1, const float* __restrict__ W2) {
    const int n4 = (4 * 16384 + 2 * 32768) / 4;   // 32768
    for (int i = blockIdx.x * blockDim.x + threadIdx.x; i < n4; i += gridDim.x * blockDim.x) {
        const float* src;
        __nv_bfloat16* dst;
        int off;
        if      (i < 4096)  { src = Wq; dst = g_Wqb; off = i; }
        else if (i < 8192)  { src = Wk; dst = g_Wkb; off = i - 4096; }
        else if (i < 12288) { src = Wv; dst = g_Wvb; off = i - 8192; }
        else if (i < 16384) { src = Wo; dst = g_Wob; off = i - 12288; }
        else if (i < 24576) { src = W1; dst = g_W1b; off = i - 16384; }
        else                { src = W2; dst = g_W2b; off = i - 24576; }
        float4 v = *(const float4*)(src + (size_t)off * 4);
        uint32_t* d = (uint32_t*)dst + off * 2;
        d[0] = packbf(v.x, v.y);
        d[1] = packbf(v.z, v.w);
    }
}

// ---------------------------------------------------------------------------
// Kernel 1: QKV — grid (488, 3), one weight per CTA, 2 CTA/SM.
// ---------------------------------------------------------------------------
__global__ void __launch_bounds__(256, 2) k_qkv(const float* __restrict__ x,
                                                const float* __restrict__ bq,
                                                const float* __restrict__ bk,
                                                const float* __restrict__ bv) {
    extern __shared__ char sm[];
    const uint32_t smB = (uint32_t)__cvta_generic_to_shared(sm);
    const uint32_t aTile = smB;
    const uint32_t bBase = smB + ATILE_BYTES;
    const int row0 = blockIdx.x << 7;
    const int which = blockIdx.y;

    const __nv_bfloat16* W = (which == 0) ? g_Wqb : (which == 1) ? g_Wkb : g_Wvb;
    const float* bias      = (which == 0) ? bq : (which == 1) ? bk : bv;
    __nv_bfloat16* out     = (which == 0) ? g_qb : (which == 1) ? g_kb : g_vb;
    const float scale      = (which == 0) ? QSCALE : 1.f;

    const int tid  = threadIdx.x;
    const int warp = tid >> 5;
    const int lane = tid & 31;
    const int gid  = lane >> 2;
    const int tig  = lane & 3;
    const int wm   = warp >> 2;
    const int wn   = warp & 3;

    #pragma unroll
    for (int s = 0; s < 4; s++)
        fill_Bchunk(bBase + s * B_SLOT, W, D_DIM, 0, s << 5);
    cp_commit();
    fill_A_from_f32(sm, 0, x, D_DIM, row0);
    cp_wait<0>();
    __syncthreads();

    float acc[4][4][4];
    zero_acc(acc);
    #pragma unroll
    for (int ch = 0; ch < 4; ch++)
        mma_chunk(aTile, ATILE_STRIDE, bBase + ch * B_SLOT, ch, acc, wm, wn, lane);

    #pragma unroll
    for (int mt = 0; mt < 4; mt++) {
        int r0 = row0 + wm * 64 + mt * 16 + gid;
        int r1 = r0 + 8;
        #pragma unroll
        for (int nt = 0; nt < 4; nt++) {
            int col = wn * 32 + nt * 8 + (tig << 1);
            float b0 = bias[col], b1 = bias[col + 1];
            if (r0 < R_TOTAL)
                *(uint32_t*)(out + (size_t)r0 * D_DIM + col) =
                    packbf((acc[mt][nt][0] + b0) * scale, (acc[mt][nt][1] + b1) * scale);
            if (r1 < R_TOTAL)
                *(uint32_t*)(out + (size_t)r1 * D_DIM + col) =
                    packbf((acc[mt][nt][2] + b0) * scale, (acc[mt][nt][3] + b1) * scale);
        }
    }
}

// ---------------------------------------------------------------------------
// Kernel 2: attention per (b,h,t). grid = 1536, block = 256. (proven R8 form)
// ---------------------------------------------------------------------------
__global__ void __launch_bounds__(256) attn_kernel() {
    __shared__ __align__(16) uint32_t Qs[NKP * 8];
    __shared__ __align__(16) uint32_t Ks[NKP * 12];
    __shared__ __align__(16) uint32_t Vt[24 * (VT_STRIDE / 2)];

    const int bid = blockIdx.x;
    const int t = bid % TT;
    const int h = (bid / TT) % H_HEADS;
    const int b = bid / (TT * H_HEADS);
    const int row0 = (b * TT + t) * NN;
    const int hoff = h * HD;
    const int tid = threadIdx.x;

    __nv_bfloat16* Vtb = (__nv_bfloat16*)Vt;

    for (int idx = tid; idx < NKP * 2; idx += 256) {
        int m = idx >> 1;
        int seg = idx & 1;
        uint4 qv, kv, vv;
        if (m < NN) {
            size_t base = (size_t)(row0 + m) * D_DIM + hoff + seg * 8;
            qv = *(const uint4*)(g_qb + base);
            kv = *(const uint4*)(g_kb + base);
            vv = *(const uint4*)(g_vb + base);
        } else {
            qv = kv = vv = make_uint4(0, 0, 0, 0);
        }
        *(uint4*)(Qs + m * 8 + seg * 4) = qv;
        *(uint4*)(Ks + m * 12 + seg * 4) = kv;
        int d0 = seg * 8;
        uint32_t vu[4] = {vv.x, vv.y, vv.z, vv.w};
        #pragma unroll
        for (int j = 0; j < 4; j++) {
            __nv_bfloat162 p = *(__nv_bfloat162*)&vu[j];
            Vtb[(d0 + 2 * j)     * VT_STRIDE + m] = p.x;
            Vtb[(d0 + 2 * j + 1) * VT_STRIDE + m] = p.y;
        }
    }
    for (int i = tid; i < 8 * (VT_STRIDE / 2); i += 256) {
        int r = 16 + i / (VT_STRIDE / 2);
        int cu = i % (VT_STRIDE / 2);
        int m = cu * 2;
        uint32_t val = 0;
        if (r == 16) {
            if (m + 1 < NN)      val = 0x3F803F80u;
            else if (m < NN)     val = 0x00003F80u;
        }
        Vt[r * (VT_STRIDE / 2) + cu] = val;
    }
    __syncthreads();

    const int warp = tid >> 5;
    const int lane = tid & 31;
    const int gid  = lane >> 2;
    const int tig  = lane & 3;

    const int rowInTile = (lane & 7) + ((lane >> 4) << 3);
    const uint32_t off16 = (uint32_t)(lane & 8) << 1;
    const uint32_t ksSm = (uint32_t)__cvta_generic_to_shared(Ks);
    const uint32_t vtSm = (uint32_t)__cvta_generic_to_shared(Vt);
    const uint32_t kLane  = ksSm + (uint32_t)rowInTile * 48 + off16;
    const uint32_t vLane  = vtSm + (uint32_t)rowInTile * (VT_STRIDE * 2) + off16;
    const uint32_t v1Lane = vtSm + (uint32_t)(16 + (lane & 7)) * (VT_STRIDE * 2) + off16;

    for (int mt = warp; mt < 21; mt += 8) {
        const int m0 = mt << 4;
        uint32_t qa[4];
        qa[0] = Qs[(m0 + gid) * 8 + tig];
        qa[1] = Qs[(m0 + gid + 8) * 8 + tig];
        qa[2] = Qs[(m0 + gid) * 8 + tig + 4];
        qa[3] = Qs[(m0 + gid + 8) * 8 + tig + 4];

        float oc0[4] = {0.f, 0.f, 0.f, 0.f};
        float oc1[4] = {0.f, 0.f, 0.f, 0.f};
        float oc2[4] = {0.f, 0.f, 0.f, 0.f};

        for (int j = 0; j < 21; j++) {
            float c0[4] = {0.f, 0.f, 0.f, 0.f};
            float c1[4] = {0.f, 0.f, 0.f, 0.f};
            uint32_t kr[4];
            ldsm_x4(kr, kLane + (uint32_t)j * (16 * 48));
            mma_bf16(c0, qa, kr);
            mma_bf16(c1, qa, kr + 2);

            float p00 = ex2(c0[0]);
            float p01 = ex2(c0[1]);
            float p02 = ex2(c0[2]);
            float p03 = ex2(c0[3]);
            float p10 = ex2(c1[0]);
            float p11 = ex2(c1[1]);
            float p12 = ex2(c1[2]);
            float p13 = ex2(c1[3]);

            uint32_t pa[4];
            pa[0] = packbf(p00, p01);
            pa[1] = packbf(p02, p03);
            pa[2] = packbf(p10, p11);
            pa[3] = packbf(p12, p13);

            uint32_t vr[4], v1r[2];
            ldsm_x4(vr, vLane + (uint32_t)j * 32);
            ldsm_x2(v1r, v1Lane + (uint32_t)j * 32);
            mma_bf16(oc0, pa, vr);
            mma_bf16(oc1, pa, vr + 2);
            mma_bf16(oc2, pa, v1r);
        }

        float rs0 = __shfl_sync(0xffffffffu, oc2[0], lane & ~3);
        float rs1 = __shfl_sync(0xffffffffu, oc2[2], lane & ~3);
        float i0 = 1.f / rs0;
        float i1 = 1.f / rs1;

        int r0 = m0 + gid;
        int r1 = m0 + gid + 8;
        if (r0 < NN) {
            __nv_bfloat16* op = g_attb + (size_t)(row0 + r0) * D_DIM + hoff;
            *(uint32_t*)(op + 2 * tig)     = packbf(oc0[0] * i0, oc0[1] * i0);
            *(uint32_t*)(op + 8 + 2 * tig) = packbf(oc1[0] * i0, oc1[1] * i0);
        }
        if (r1 < NN) {
            __nv_bfloat16* op = g_attb + (size_t)(row0 + r1) * D_DIM + hoff;
            *(uint32_t*)(op + 2 * tig)     = packbf(oc0[2] * i1, oc0[3] * i1);
            *(uint32_t*)(op + 8 + 2 * tig) = packbf(oc1[2] * i1, oc1[3] * i1);
        }
    }
}

// ---------------------------------------------------------------------------
// Kernel 3: h = LN1(x + att @ Wo + bo). 2 CTA/SM, two-pass LN epilogue.
// ---------------------------------------------------------------------------
__global__ void __launch_bounds__(256, 2) k_projo_ln1(const float* __restrict__ x,
                                                      const float* __restrict__ bo,
                                                      const float* __restrict__ g1,
                                                      const float* __restrict__ b1) {
    extern __shared__ char sm[];
    float* smf = (float*)sm;
    const uint32_t smB = (uint32_t)__cvta_generic_to_shared(sm);
    const uint32_t aTile = smB;
    const uint32_t bBase = smB + ATILE_BYTES;
    const int row0 = blockIdx.x << 7;

    const int tid  = threadIdx.x;
    const int warp = tid >> 5;
    const int lane = tid & 31;
    const int wm   = warp >> 2;
    const int wn   = warp & 3;

    fill_A_bf16(aTile, g_attb, D_DIM, row0);
    #pragma unroll
    for (int s = 0; s < 4; s++)
        fill_Bchunk(bBase + s * B_SLOT, g_Wob, D_DIM, 0, s << 5);
    cp_commit();
    cp_wait<0>();
    __syncthreads();

    float acc[4][4][4];
    zero_acc(acc);
    #pragma unroll
    for (int ch = 0; ch < 4; ch++)
        mma_chunk(aTile, ATILE_STRIDE, bBase + ch * B_SLOT, ch, acc, wm, wn, lane);

    __syncthreads();
    stage_c(smf, acc);

    ln_epilogue(smf, row0, x, bo, g1, b1, g_h);
}

// ---------------------------------------------------------------------------
// Kernel 4 (FUSED): out = LN2(h + gelu(h@W1+b1)@W2 + b2).
// Layout: A [0,34816), mid [34816,102400) stride 528, wbuf [102400,172032).
// ---------------------------------------------------------------------------
__global__ void __launch_bounds__(256) k_ffn_fused(const float* __restrict__ b1,
                                                   const float* __restrict__ b2,
                                                   const float* __restrict__ g2,
                                                   const float* __restrict__ bt2,
                                                   float* __restrict__ out) {
    extern __shared__ char sm[];
    float* smf = (float*)sm;
    const uint32_t smB = (uint32_t)__cvta_generic_to_shared(sm);
    const uint32_t aTile = smB;
    const uint32_t midTile = smB + ATILE_BYTES;
    const uint32_t wBase = midTile + MID_BYTES;
    const int row0 = blockIdx.x << 7;

    const int tid  = threadIdx.x;
    const int warp = tid >> 5;
    const int lane = tid & 31;
    const int gid  = lane >> 2;
    const int tig  = lane & 3;
    const int wm   = warp >> 2;
    const int wn   = warp & 3;

    #pragma unroll
    for (int s = 0; s < 8; s++)
        fill_Bchunk(wBase + s * B_SLOT, g_W1b, F_DIM, (s >> 2) << 7, (s & 3) << 5);
    cp_commit();
    fill_A_from_f32(sm, 0, g_h, D_DIM, row0);
    cp_wait<0>();
    __syncthreads();

    float acc[4][4][4];
    __nv_bfloat16* midb = (__nv_bfloat16*)(sm + ATILE_BYTES);

    // GEMM1: two N-halves sequentially with ONE acc set; mid is separate smem.
    #pragma unroll
    for (int w = 0; w < 2; w++) {
        zero_acc(acc);
        #pragma unroll
        for (int ch = 0; ch < 4; ch++)
            mma_chunk(aTile, ATILE_STRIDE, wBase + (w * 4 + ch) * B_SLOT, ch, acc, wm, wn, lane);

        const int col0 = w << 7;
        #pragma unroll
        for (int mt = 0; mt < 4; mt++) {
            int lr0 = wm * 64 + mt * 16 + gid;
            int lr1 = lr0 + 8;
            #pragma unroll
            for (int nt = 0; nt < 4; nt++) {
                int col = col0 + wn * 32 + nt * 8 + (tig << 1);
                float bb0 = b1[col], bb1 = b1[col + 1];
                float v0 = acc[mt][nt][0] + bb0;
                float v1 = acc[mt][nt][1] + bb1;
                float v2 = acc[mt][nt][2] + bb0;
                float v3 = acc[mt][nt][3] + bb1;
                float e0 = 0.5f * v0 * (1.f + erff(v0 * 0.70710678118654752f));
                float e1 = 0.5f * v1 * (1.f + erff(v1 * 0.70710678118654752f));
                float e2 = 0.5f * v2 * (1.f + erff(v2 * 0.70710678118654752f));
                float e3 = 0.5f * v3 * (1.f + erff(v3 * 0.70710678118654752f));
                *(uint32_t*)((char*)midb + lr0 * MID_STRIDE + col * 2) = packbf(e0, e1);
                *(uint32_t*)((char*)midb + lr1 * MID_STRIDE + col * 2) = packbf(e2, e3);
            }
        }
    }
    __syncthreads();   // all W1 reads + mid writes done

    // Refill wbuf with W2 (8 slots, k = 256)
    #pragma unroll
    for (int s = 0; s < 8; s++)
        fill_Bchunk(wBase + s * B_SLOT, g_W2b, D_DIM, 0, s << 5);
    cp_commit();
    cp_wait<0>();
    __syncthreads();

    // GEMM2: mid(128x256) @ W2(256x128); ch selects mid column slice (0..7).
    zero_acc(acc);
    #pragma unroll
    for (int ch = 0; ch < 8; ch++)
        mma_chunk(midTile, MID_STRIDE, wBase + ch * B_SLOT, ch, acc, wm, wn, lane);

    __syncthreads();
    stage_c(smf, acc);

    ln_epilogue(smf, row0, g_h, b2, g2, bt2, out);
}

// ---------------------------------------------------------------------------
extern "C" void kernel_launch(void* const* d_in, const int* in_sizes, int n_in,
                              void* d_out, int out_size) {
    const float* x     = (const float*)d_in[0];
    const float* Wq    = (const float*)d_in[1];
    const float* bq    = (const float*)d_in[2];
    const float* Wk    = (const float*)d_in[3];
    const float* bk    = (const float*)d_in[4];
    const float* Wv    = (const float*)d_in[5];
    const float* bv    = (const float*)d_in[6];
    const float* Wo    = (const float*)d_in[7];
    const float* bo    = (const float*)d_in[8];
    const float* ln1_g = (const float*)d_in[9];
    const float* ln1_b = (const float*)d_in[10];
    const float* W1    = (const float*)d_in[11];
    const float* b1    = (const float*)d_in[12];
    const float* W2    = (const float*)d_in[13];
    const float* b2    = (const float*)d_in[14];
    const float* ln2_g = (const float*)d_in[15];
    const float* ln2_b = (const float*)d_in[16];
    float* out = (float*)d_out;

    cudaFuncSetAttribute(k_qkv,       cudaFuncAttributeMaxDynamicSharedMemorySize, QKV_SMEM);
    cudaFuncSetAttribute(k_projo_ln1, cudaFuncAttributeMaxDynamicSharedMemorySize, PROJO_SMEM);
    cudaFuncSetAttribute(k_ffn_fused, cudaFuncAttributeMaxDynamicSharedMemorySize, FFNF_SMEM);

    k_cvt_w<<<64, 512>>>(Wq, Wk, Wv, Wo, W1, W2);
    k_qkv<<<dim3(M_TILES, 3), 256, QKV_SMEM>>>(x, bq, bk, bv);
    attn_kernel<<<NB * H_HEADS * TT, 256>>>();
    k_projo_ln1<<<M_TILES, 256, PROJO_SMEM>>>(x, bo, ln1_g, ln1_b);
    k_ffn_fused<<<M_TILES, 256, FFNF_SMEM>>>(b1, b2, ln2_g, ln2_b, out);
}

// round 15
// speedup vs baseline: 1.4371x; 1.0212x over previous
#include <cuda_runtime.h>
#include <cuda_bf16.h>
#include <math.h>
#include <stdint.h>

// Problem constants
#define NB 16
#define TT 12
#define NN 325
#define D_DIM 128
#define F_DIM 256
#define H_HEADS 8
#define HD 16
#define R_TOTAL (NB*TT*NN)   // 62400
#define M_TILES ((R_TOTAL + 127) / 128)   // 488

// Attention padding
#define NKP 336
#define VT_STRIDE 344

// log2(e)/4 folded into q so attention uses plain exp2
#define QSCALE 0.36067376022224085f

// ---------------------------------------------------------------------------
// Scratch (device globals: allocation-guard safe)
// ---------------------------------------------------------------------------
__device__ __nv_bfloat16 g_qb [R_TOTAL * D_DIM];   // pre-scaled by QSCALE
__device__ __nv_bfloat16 g_kb [R_TOTAL * D_DIM];
__device__ __nv_bfloat16 g_vb [R_TOTAL * D_DIM];
__device__ __nv_bfloat16 g_attb[R_TOTAL * D_DIM];
__device__ __nv_bfloat16 g_Wqb[D_DIM * D_DIM];
__device__ __nv_bfloat16 g_Wkb[D_DIM * D_DIM];
__device__ __nv_bfloat16 g_Wvb[D_DIM * D_DIM];
__device__ __nv_bfloat16 g_Wob[D_DIM * D_DIM];
__device__ __nv_bfloat16 g_W1b[D_DIM * F_DIM];
__device__ __nv_bfloat16 g_W2b[F_DIM * D_DIM];

// ---------------------------------------------------------------------------
// Common helpers
// ---------------------------------------------------------------------------
__device__ __forceinline__ uint32_t packbf(float x, float y) {  // lo=x, hi=y
    uint32_t r;
    asm("cvt.rn.bf16x2.f32 %0, %1, %2;" : "=r"(r) : "f"(y), "f"(x));
    return r;
}

__device__ __forceinline__ float ex2(float x) {
    float r;
    asm("ex2.approx.f32 %0, %1;" : "=f"(r) : "f"(x));
    return r;
}

__device__ __forceinline__ void mma_bf16(float c[4], const uint32_t a[4], const uint32_t b[2]) {
    asm volatile(
        "mma.sync.aligned.m16n8k16.row.col.f32.bf16.bf16.f32 "
        "{%0,%1,%2,%3}, {%4,%5,%6,%7}, {%8,%9}, {%0,%1,%2,%3};"
        : "+f"(c[0]), "+f"(c[1]), "+f"(c[2]), "+f"(c[3])
        : "r"(a[0]), "r"(a[1]), "r"(a[2]), "r"(a[3]), "r"(b[0]), "r"(b[1]));
}

__device__ __forceinline__ void ldsm_x4(uint32_t r[4], uint32_t addr) {
    asm volatile("ldmatrix.sync.aligned.m8n8.x4.shared.b16 {%0,%1,%2,%3}, [%4];"
        : "=r"(r[0]), "=r"(r[1]), "=r"(r[2]), "=r"(r[3]) : "r"(addr));
}
__device__ __forceinline__ void ldsm_x2(uint32_t r[2], uint32_t addr) {
    asm volatile("ldmatrix.sync.aligned.m8n8.x2.shared.b16 {%0,%1}, [%2];"
        : "=r"(r[0]), "=r"(r[1]) : "r"(addr));
}
__device__ __forceinline__ void ldsm_x2t(uint32_t r[2], uint32_t addr) {
    asm volatile("ldmatrix.sync.aligned.m8n8.x2.trans.shared.b16 {%0,%1}, [%2];"
        : "=r"(r[0]), "=r"(r[1]) : "r"(addr));
}

__device__ __forceinline__ void cp16(uint32_t smaddr, const void* gaddr) {
    asm volatile("cp.async.cg.shared.global [%0], [%1], 16;" :: "r"(smaddr), "l"(gaddr));
}
__device__ __forceinline__ void cp_commit() {
    asm volatile("cp.async.commit_group;");
}
template <int N>
__device__ __forceinline__ void cp_wait() {
    asm volatile("cp.async.wait_group %0;" :: "n"(N));
}

// ---------------------------------------------------------------------------
// GEMM geometry: CTA 128x128 out tile, 8 warps (2x4), warp 64x32.
// ---------------------------------------------------------------------------
#define BS_U32 68
#define B_SLOT (32 * BS_U32 * 4)            // 8704
#define ATILE_STRIDE 272
#define ATILE_BYTES (128 * ATILE_STRIDE)    // 34816
#define MID_STRIDE 528
#define MID_BYTES (128 * MID_STRIDE)        // 67584
#define CS_STRIDE 132                       // 528B rows -> LDS.128 epilogues
#define C_BYTES (128 * CS_STRIDE * 4)       // 67584

#define QKV_SMEM  (ATILE_BYTES + 4 * B_SLOT)    // 69632 -> 2 CTA/SM

// Fused block2 smem regions
#define FB_R0 0                              // attbA+Wo -> C -> h_fp32 (69632)
#define FB_R1 69632                          // h_bf16 A-tile (34816)
#define FB_R2 104448                         // 4 streaming W slots (34816)
#define FB_R3 139264                         // mid bf16 -> C2 (67584)
#define FB_SMEM 206848

// Fill bf16 A tile by converting fp32 source rows (LDG float4 -> STS 8B).
__device__ __forceinline__ void fill_A_from_f32(char* sm, uint32_t aTileOff,
                                                const float* __restrict__ A,
                                                int lda, int row0) {
    const int tid = threadIdx.x;
    #pragma unroll
    for (int it = 0; it < 16; it++) {
        int idx = tid + it * 256;
        int r = idx >> 5, c4 = (idx & 31) << 2;
        int row = row0 + r;
        if (row > R_TOTAL - 1) row = R_TOTAL - 1;
        float4 v = *(const float4*)(A + (size_t)row * lda + c4);
        uint32_t* p = (uint32_t*)(sm + aTileOff + r * ATILE_STRIDE + c4 * 2);
        p[0] = packbf(v.x, v.y);
        p[1] = packbf(v.z, v.w);
    }
}

// Fill bf16 A tile from bf16 source via cp.async (no commit).
__device__ __forceinline__ void fill_A_bf16(uint32_t aTile,
                                            const __nv_bfloat16* __restrict__ A,
                                            int lda, int row0) {
    const int tid = threadIdx.x;
    #pragma unroll
    for (int it = 0; it < 8; it++) {
        int idx = tid + it * 256;
        int r = idx >> 4, seg = idx & 15;
        int row = row0 + r;
        if (row > R_TOTAL - 1) row = R_TOTAL - 1;
        cp16(aTile + r * ATILE_STRIDE + seg * 16,
             A + (size_t)row * lda + seg * 8);
    }
}

// Fill one 32-k B chunk (no commit)
__device__ __forceinline__ void fill_Bchunk(uint32_t dst,
                                            const __nv_bfloat16* __restrict__ B, int ldb,
                                            int bcol0, int kofs) {
    const int tid = threadIdx.x;
    #pragma unroll
    for (int it = 0; it < 2; it++) {
        int idx = tid + it * 256;
        int k = idx >> 4, seg = idx & 15;
        cp16(dst + k * (BS_U32 * 4) + seg * 16,
             B + (size_t)(kofs + k) * ldb + bcol0 + seg * 8);
    }
}

// One 32-k chunk of MMAs; A tile row stride parameterized; ch selects the
// 64-byte (32-bf16) column slice of A rows.
__device__ __forceinline__ void mma_chunk(uint32_t aTile, uint32_t aStride,
                                          uint32_t bSlot, int ch,
                                          float acc[4][4][4], int wm, int wn, int lane) {
    const uint32_t aBase = aTile + (uint32_t)(wm * 64 + (lane & 15)) * aStride
                         + (uint32_t)(ch * 64) + ((uint32_t)(lane >> 4) << 4);
    const uint32_t bBase = bSlot + (uint32_t)(lane & 15) * (BS_U32 * 4) + (uint32_t)wn * 64;
    #pragma unroll
    for (int ks = 0; ks < 2; ks++) {
        uint32_t af[4][4], bfr[4][2];
        #pragma unroll
        for (int mt = 0; mt < 4; mt++)
            ldsm_x4(af[mt], aBase + mt * (16 * aStride) + ks * 32);
        #pragma unroll
        for (int nt = 0; nt < 4; nt++)
            ldsm_x2t(bfr[nt], bBase + ks * (16 * BS_U32 * 4) + nt * 16);
        #pragma unroll
        for (int mt = 0; mt < 4; mt++)
            #pragma unroll
            for (int nt = 0; nt < 4; nt++)
                mma_bf16(acc[mt][nt], af[mt], bfr[nt]);
    }
}

__device__ __forceinline__ void zero_acc(float acc[4][4][4]) {
    #pragma unroll
    for (int i = 0; i < 4; i++)
        #pragma unroll
        for (int j = 0; j < 4; j++)
            #pragma unroll
            for (int r = 0; r < 4; r++) acc[i][j][r] = 0.f;
}

// Stage accumulators to smem C[128][132] at smf.
__device__ __forceinline__ void stage_c(float* smf, float acc[4][4][4]) {
    const int tid  = threadIdx.x;
    const int warp = tid >> 5;
    const int lane = tid & 31;
    const int gid  = lane >> 2;
    const int tig  = lane & 3;
    const int wm   = warp >> 2;
    const int wn   = warp & 3;
    #pragma unroll
    for (int mt = 0; mt < 4; mt++) {
        #pragma unroll
        for (int nt = 0; nt < 4; nt++) {
            int row = wm * 64 + mt * 16 + gid;
            int col = wn * 32 + nt * 8 + (tig << 1);
            *(float2*)(smf + row * CS_STRIDE + col)       = make_float2(acc[mt][nt][0], acc[mt][nt][1]);
            *(float2*)(smf + (row + 8) * CS_STRIDE + col) = make_float2(acc[mt][nt][2], acc[mt][nt][3]);
        }
    }
    __syncthreads();
}

// ---------------------------------------------------------------------------
// Weight conversion (fp32 -> bf16)
// ---------------------------------------------------------------------------
__global__ void k_cvt_w(const float* __restrict__ Wq, const float* __restrict__ Wk,
                        const float* __restrict__ Wv, const float* __restrict__ Wo,
                        const float* __restrict__ W1, const float* __restrict__ W2) {
    const int n4 = (4 * 16384 + 2 * 32768) / 4;   // 32768
    for (int i = blockIdx.x * blockDim.x + threadIdx.x; i < n4; i += gridDim.x * blockDim.x) {
        const float* src;
        __nv_bfloat16* dst;
        int off;
        if      (i < 4096)  { src = Wq; dst = g_Wqb; off = i; }
        else if (i < 8192)  { src = Wk; dst = g_Wkb; off = i - 4096; }
        else if (i < 12288) { src = Wv; dst = g_Wvb; off = i - 8192; }
        else if (i < 16384) { src = Wo; dst = g_Wob; off = i - 12288; }
        else if (i < 24576) { src = W1; dst = g_W1b; off = i - 16384; }
        else                { src = W2; dst = g_W2b; off = i - 24576; }
        float4 v = *(const float4*)(src + (size_t)off * 4);
        uint32_t* d = (uint32_t*)dst + off * 2;
        d[0] = packbf(v.x, v.y);
        d[1] = packbf(v.z, v.w);
    }
}

// ---------------------------------------------------------------------------
// Kernel 1: QKV — grid (488, 3), one weight per CTA, 2 CTA/SM.
// ---------------------------------------------------------------------------
__global__ void __launch_bounds__(256, 2) k_qkv(const float* __restrict__ x,
                                                const float* __restrict__ bq,
                                                const float* __restrict__ bk,
                                                const float* __restrict__ bv) {
    extern __shared__ char sm[];
    const uint32_t smB = (uint32_t)__cvta_generic_to_shared(sm);
    const uint32_t aTile = smB;
    const uint32_t bBase = smB + ATILE_BYTES;
    const int row0 = blockIdx.x << 7;
    const int which = blockIdx.y;

    const __nv_bfloat16* W = (which == 0) ? g_Wqb : (which == 1) ? g_Wkb : g_Wvb;
    const float* bias      = (which == 0) ? bq : (which == 1) ? bk : bv;
    __nv_bfloat16* out     = (which == 0) ? g_qb : (which == 1) ? g_kb : g_vb;
    const float scale      = (which == 0) ? QSCALE : 1.f;

    const int tid  = threadIdx.x;
    const int warp = tid >> 5;
    const int lane = tid & 31;
    const int gid  = lane >> 2;
    const int tig  = lane & 3;
    const int wm   = warp >> 2;
    const int wn   = warp & 3;

    #pragma unroll
    for (int s = 0; s < 4; s++)
        fill_Bchunk(bBase + s * B_SLOT, W, D_DIM, 0, s << 5);
    cp_commit();
    fill_A_from_f32(sm, 0, x, D_DIM, row0);
    cp_wait<0>();
    __syncthreads();

    float acc[4][4][4];
    zero_acc(acc);
    #pragma unroll
    for (int ch = 0; ch < 4; ch++)
        mma_chunk(aTile, ATILE_STRIDE, bBase + ch * B_SLOT, ch, acc, wm, wn, lane);

    #pragma unroll
    for (int mt = 0; mt < 4; mt++) {
        int r0 = row0 + wm * 64 + mt * 16 + gid;
        int r1 = r0 + 8;
        #pragma unroll
        for (int nt = 0; nt < 4; nt++) {
            int col = wn * 32 + nt * 8 + (tig << 1);
            float b0 = bias[col], b1 = bias[col + 1];
            if (r0 < R_TOTAL)
                *(uint32_t*)(out + (size_t)r0 * D_DIM + col) =
                    packbf((acc[mt][nt][0] + b0) * scale, (acc[mt][nt][1] + b1) * scale);
            if (r1 < R_TOTAL)
                *(uint32_t*)(out + (size_t)r1 * D_DIM + col) =
                    packbf((acc[mt][nt][2] + b0) * scale, (acc[mt][nt][3] + b1) * scale);
        }
    }
}

// ---------------------------------------------------------------------------
// Kernel 2: attention per (b,h,t). grid = 1536, block = 256. (proven R8 form)
// ---------------------------------------------------------------------------
__global__ void __launch_bounds__(256) attn_kernel() {
    __shared__ __align__(16) uint32_t Qs[NKP * 8];
    __shared__ __align__(16) uint32_t Ks[NKP * 12];
    __shared__ __align__(16) uint32_t Vt[24 * (VT_STRIDE / 2)];

    const int bid = blockIdx.x;
    const int t = bid % TT;
    const int h = (bid / TT) % H_HEADS;
    const int b = bid / (TT * H_HEADS);
    const int row0 = (b * TT + t) * NN;
    const int hoff = h * HD;
    const int tid = threadIdx.x;

    __nv_bfloat16* Vtb = (__nv_bfloat16*)Vt;

    for (int idx = tid; idx < NKP * 2; idx += 256) {
        int m = idx >> 1;
        int seg = idx & 1;
        uint4 qv, kv, vv;
        if (m < NN) {
            size_t base = (size_t)(row0 + m) * D_DIM + hoff + seg * 8;
            qv = *(const uint4*)(g_qb + base);
            kv = *(const uint4*)(g_kb + base);
            vv = *(const uint4*)(g_vb + base);
        } else {
            qv = kv = vv = make_uint4(0, 0, 0, 0);
        }
        *(uint4*)(Qs + m * 8 + seg * 4) = qv;
        *(uint4*)(Ks + m * 12 + seg * 4) = kv;
        int d0 = seg * 8;
        uint32_t vu[4] = {vv.x, vv.y, vv.z, vv.w};
        #pragma unroll
        for (int j = 0; j < 4; j++) {
            __nv_bfloat162 p = *(__nv_bfloat162*)&vu[j];
            Vtb[(d0 + 2 * j)     * VT_STRIDE + m] = p.x;
            Vtb[(d0 + 2 * j + 1) * VT_STRIDE + m] = p.y;
        }
    }
    for (int i = tid; i < 8 * (VT_STRIDE / 2); i += 256) {
        int r = 16 + i / (VT_STRIDE / 2);
        int cu = i % (VT_STRIDE / 2);
        int m = cu * 2;
        uint32_t val = 0;
        if (r == 16) {
            if (m + 1 < NN)      val = 0x3F803F80u;
            else if (m < NN)     val = 0x00003F80u;
        }
        Vt[r * (VT_STRIDE / 2) + cu] = val;
    }
    __syncthreads();

    const int warp = tid >> 5;
    const int lane = tid & 31;
    const int gid  = lane >> 2;
    const int tig  = lane & 3;

    const int rowInTile = (lane & 7) + ((lane >> 4) << 3);
    const uint32_t off16 = (uint32_t)(lane & 8) << 1;
    const uint32_t ksSm = (uint32_t)__cvta_generic_to_shared(Ks);
    const uint32_t vtSm = (uint32_t)__cvta_generic_to_shared(Vt);
    const uint32_t kLane  = ksSm + (uint32_t)rowInTile * 48 + off16;
    const uint32_t vLane  = vtSm + (uint32_t)rowInTile * (VT_STRIDE * 2) + off16;
    const uint32_t v1Lane = vtSm + (uint32_t)(16 + (lane & 7)) * (VT_STRIDE * 2) + off16;

    for (int mt = warp; mt < 21; mt += 8) {
        const int m0 = mt << 4;
        uint32_t qa[4];
        qa[0] = Qs[(m0 + gid) * 8 + tig];
        qa[1] = Qs[(m0 + gid + 8) * 8 + tig];
        qa[2] = Qs[(m0 + gid) * 8 + tig + 4];
        qa[3] = Qs[(m0 + gid + 8) * 8 + tig + 4];

        float oc0[4] = {0.f, 0.f, 0.f, 0.f};
        float oc1[4] = {0.f, 0.f, 0.f, 0.f};
        float oc2[4] = {0.f, 0.f, 0.f, 0.f};

        for (int j = 0; j < 21; j++) {
            float c0[4] = {0.f, 0.f, 0.f, 0.f};
            float c1[4] = {0.f, 0.f, 0.f, 0.f};
            uint32_t kr[4];
            ldsm_x4(kr, kLane + (uint32_t)j * (16 * 48));
            mma_bf16(c0, qa, kr);
            mma_bf16(c1, qa, kr + 2);

            float p00 = ex2(c0[0]);
            float p01 = ex2(c0[1]);
            float p02 = ex2(c0[2]);
            float p03 = ex2(c0[3]);
            float p10 = ex2(c1[0]);
            float p11 = ex2(c1[1]);
            float p12 = ex2(c1[2]);
            float p13 = ex2(c1[3]);

            uint32_t pa[4];
            pa[0] = packbf(p00, p01);
            pa[1] = packbf(p02, p03);
            pa[2] = packbf(p10, p11);
            pa[3] = packbf(p12, p13);

            uint32_t vr[4], v1r[2];
            ldsm_x4(vr, vLane + (uint32_t)j * 32);
            ldsm_x2(v1r, v1Lane + (uint32_t)j * 32);
            mma_bf16(oc0, pa, vr);
            mma_bf16(oc1, pa, vr + 2);
            mma_bf16(oc2, pa, v1r);
        }

        float rs0 = __shfl_sync(0xffffffffu, oc2[0], lane & ~3);
        float rs1 = __shfl_sync(0xffffffffu, oc2[2], lane & ~3);
        float i0 = 1.f / rs0;
        float i1 = 1.f / rs1;

        int r0 = m0 + gid;
        int r1 = m0 + gid + 8;
        if (r0 < NN) {
            __nv_bfloat16* op = g_attb + (size_t)(row0 + r0) * D_DIM + hoff;
            *(uint32_t*)(op + 2 * tig)     = packbf(oc0[0] * i0, oc0[1] * i0);
            *(uint32_t*)(op + 8 + 2 * tig) = packbf(oc1[0] * i0, oc1[1] * i0);
        }
        if (r1 < NN) {
            __nv_bfloat16* op = g_attb + (size_t)(row0 + r1) * D_DIM + hoff;
            *(uint32_t*)(op + 2 * tig)     = packbf(oc0[2] * i1, oc0[3] * i1);
            *(uint32_t*)(op + 8 + 2 * tig) = packbf(oc1[2] * i1, oc1[3] * i1);
        }
    }
}

// ---------------------------------------------------------------------------
// Kernel 3 (FULLY FUSED): out = LN2(h + gelu(h@W1+b1)@W2 + b2)
//                         where h = LN1(x + attb@Wo + bo).
// h never touches DRAM. grid 488, block 256, smem 206848 (1 CTA/SM).
// Regions: R0 attbA+Wo -> C -> h_fp32 (stride 132); R1 h_bf16 (stride 272);
//          R2 4 streaming W slots; R3 mid (stride 528) -> C2 (stride 132).
// ---------------------------------------------------------------------------
__global__ void __launch_bounds__(256) k_block2(const float* __restrict__ x,
                                                const float* __restrict__ bo,
                                                const float* __restrict__ g1,
                                                const float* __restrict__ b1ln,
                                                const float* __restrict__ b1,
                                                const float* __restrict__ b2,
                                                const float* __restrict__ g2,
                                                const float* __restrict__ bt2,
                                                float* __restrict__ out) {
    extern __shared__ char sm[];
    const uint32_t smB = (uint32_t)__cvta_generic_to_shared(sm);
    const int row0 = blockIdx.x << 7;

    const int tid  = threadIdx.x;
    const int warp = tid >> 5;
    const int lane = tid & 31;
    const int gid  = lane >> 2;
    const int tig  = lane & 3;
    const int wm   = warp >> 2;
    const int wn   = warp & 3;
    const int lrow = tid >> 1;
    const int half = tid & 1;

    float* hF   = (float*)(sm + FB_R0);          // later: h fp32, stride 132
    float* c2F  = (float*)(sm + FB_R3);          // later: GEMM2 C, stride 132

    // --- Phase 1: fill attbA (R0) + Wo (R0+34816) [group0]; prefetch W1 0-3 (R2) [group1]
    fill_A_bf16(smB + FB_R0, g_attb, D_DIM, row0);
    #pragma unroll
    for (int s = 0; s < 4; s++)
        fill_Bchunk(smB + FB_R0 + ATILE_BYTES + s * B_SLOT, g_Wob, D_DIM, 0, s << 5);
    cp_commit();
    #pragma unroll
    for (int s = 0; s < 4; s++)
        fill_Bchunk(smB + FB_R2 + s * B_SLOT, g_W1b, F_DIM, 0, s << 5);
    cp_commit();
    cp_wait<1>();          // group0 (attbA+Wo) complete
    __syncthreads();

    // --- GEMM0: attb @ Wo
    float acc[4][4][4];
    zero_acc(acc);
    #pragma unroll
    for (int ch = 0; ch < 4; ch++)
        mma_chunk(smB + FB_R0, ATILE_STRIDE, smB + FB_R0 + ATILE_BYTES + ch * B_SLOT,
                  ch, acc, wm, wn, lane);

    __syncthreads();                 // done reading R0 before staging C into it
    stage_c(hF, acc);                // C -> R0 (stride 132); includes sync

    // --- LN1 epilogue: h fp32 in place (R0), h bf16 -> R1
    {
        int row = row0 + lrow;
        if (row < R_TOTAL) {
            float* Cr = hF + lrow * CS_STRIDE + half * 64;
            const float* xr = x + (size_t)row * D_DIM + half * 64;
            const float* br = bo + half * 64;
            float s1 = 0.f, s2 = 0.f;
            #pragma unroll
            for (int c = 0; c < 64; c += 4) {
                float4 cv = *(const float4*)(Cr + c);
                float4 rv = *(const float4*)(xr + c);
                float4 bv = *(const float4*)(br + c);
                float v0 = cv.x + bv.x + rv.x;
                float v1 = cv.y + bv.y + rv.y;
                float v2 = cv.z + bv.z + rv.z;
                float v3 = cv.w + bv.w + rv.w;
                s1 += (v0 + v1) + (v2 + v3);
                s2 += (v0 * v0 + v1 * v1) + (v2 * v2 + v3 * v3);
            }
            s1 += __shfl_xor_sync(0xffffffffu, s1, 1);
            s2 += __shfl_xor_sync(0xffffffffu, s2, 1);
            float mean = s1 * (1.f / 128.f);
            float var  = s2 * (1.f / 128.f) - mean * mean;
            float rstd = rsqrtf(var + 1e-5f);
            const float* gr = g1 + half * 64;
            const float* btr = b1ln + half * 64;
            uint32_t* hb = (uint32_t*)(sm + FB_R1 + lrow * ATILE_STRIDE + half * 128);
            #pragma unroll
            for (int c = 0; c < 64; c += 4) {
                float4 cv = *(const float4*)(Cr + c);
                float4 rv = *(const float4*)(xr + c);
                float4 bv = *(const float4*)(br + c);
                float4 gv = *(const float4*)(gr + c);
                float4 bb = *(const float4*)(btr + c);
                float4 o;
                o.x = (cv.x + bv.x + rv.x - mean) * rstd * gv.x + bb.x;
                o.y = (cv.y + bv.y + rv.y - mean) * rstd * gv.y + bb.y;
                o.z = (cv.z + bv.z + rv.z - mean) * rstd * gv.z + bb.z;
                o.w = (cv.w + bv.w + rv.w - mean) * rstd * gv.w + bb.w;
                *(float4*)(Cr + c) = o;                  // h fp32 (LN2 residual)
                hb[c >> 1]       = packbf(o.x, o.y);     // h bf16 (GEMM1 A)
                hb[(c >> 1) + 1] = packbf(o.z, o.w);
            }
        } else {
            // keep warp convergence for shfl
            float s1 = 0.f, s2 = 0.f;
            s1 += __shfl_xor_sync(0xffffffffu, s1, 1);
            s2 += __shfl_xor_sync(0xffffffffu, s2, 1);
            (void)s1; (void)s2;
        }
    }
    cp_wait<0>();          // W1 chunks 0-3 ready (long done)
    __syncthreads();       // h_bf16 visible to all warps

    __nv_bfloat16* midb = (__nv_bfloat16*)(sm + FB_R3);

    // --- GEMM1 half 0: h @ W1[:, 0:128]
    zero_acc(acc);
    #pragma unroll
    for (int ch = 0; ch < 4; ch++)
        mma_chunk(smB + FB_R1, ATILE_STRIDE, smB + FB_R2 + ch * B_SLOT, ch, acc, wm, wn, lane);

    #pragma unroll
    for (int mt = 0; mt < 4; mt++) {
        int lr0 = wm * 64 + mt * 16 + gid;
        int lr1 = lr0 + 8;
        #pragma unroll
        for (int nt = 0; nt < 4; nt++) {
            int col = wn * 32 + nt * 8 + (tig << 1);
            float bb0 = b1[col], bb1 = b1[col + 1];
            float v0 = acc[mt][nt][0] + bb0;
            float v1 = acc[mt][nt][1] + bb1;
            float v2 = acc[mt][nt][2] + bb0;
            float v3 = acc[mt][nt][3] + bb1;
            float e0 = 0.5f * v0 * (1.f + erff(v0 * 0.70710678118654752f));
            float e1 = 0.5f * v1 * (1.f + erff(v1 * 0.70710678118654752f));
            float e2 = 0.5f * v2 * (1.f + erff(v2 * 0.70710678118654752f));
            float e3 = 0.5f * v3 * (1.f + erff(v3 * 0.70710678118654752f));
            *(uint32_t*)((char*)midb + lr0 * MID_STRIDE + col * 2) = packbf(e0, e1);
            *(uint32_t*)((char*)midb + lr1 * MID_STRIDE + col * 2) = packbf(e2, e3);
        }
    }
    __syncthreads();       // W1 0-3 reads done -> R2 reusable

    // --- GEMM1 half 1: refill R2 with W1[:, 128:256] chunks
    #pragma unroll
    for (int s = 0; s < 4; s++)
        fill_Bchunk(smB + FB_R2 + s * B_SLOT, g_W1b, F_DIM, 128, s << 5);
    cp_commit();
    cp_wait<0>();
    __syncthreads();

    zero_acc(acc);
    #pragma unroll
    for (int ch = 0; ch < 4; ch++)
        mma_chunk(smB + FB_R1, ATILE_STRIDE, smB + FB_R2 + ch * B_SLOT, ch, acc, wm, wn, lane);

    #pragma unroll
    for (int mt = 0; mt < 4; mt++) {
        int lr0 = wm * 64 + mt * 16 + gid;
        int lr1 = lr0 + 8;
        #pragma unroll
        for (int nt = 0; nt < 4; nt++) {
            int col = 128 + wn * 32 + nt * 8 + (tig << 1);
            float bb0 = b1[col], bb1 = b1[col + 1];
            float v0 = acc[mt][nt][0] + bb0;
            float v1 = acc[mt][nt][1] + bb1;
            float v2 = acc[mt][nt][2] + bb0;
            float v3 = acc[mt][nt][3] + bb1;
            float e0 = 0.5f * v0 * (1.f + erff(v0 * 0.70710678118654752f));
            float e1 = 0.5f * v1 * (1.f + erff(v1 * 0.70710678118654752f));
            float e2 = 0.5f * v2 * (1.f + erff(v2 * 0.70710678118654752f));
            float e3 = 0.5f * v3 * (1.f + erff(v3 * 0.70710678118654752f));
            *(uint32_t*)((char*)midb + lr0 * MID_STRIDE + col * 2) = packbf(e0, e1);
            *(uint32_t*)((char*)midb + lr1 * MID_STRIDE + col * 2) = packbf(e2, e3);
        }
    }
    __syncthreads();       // W1 4-7 reads + mid writes done

    // --- GEMM2: mid @ W2 (k=256, two batches of 4 chunks through R2)
    zero_acc(acc);
    #pragma unroll
    for (int batch = 0; batch < 2; batch++) {
        #pragma unroll
        for (int s = 0; s < 4; s++)
            fill_Bchunk(smB + FB_R2 + s * B_SLOT, g_W2b, D_DIM, 0, (batch * 4 + s) << 5);
        cp_commit();
        cp_wait<0>();
        __syncthreads();
        #pragma unroll
        for (int s = 0; s < 4; s++)
            mma_chunk(smB + FB_R3, MID_STRIDE, smB + FB_R2 + s * B_SLOT,
                      batch * 4 + s, acc, wm, wn, lane);
        __syncthreads();   // R2 reads done before next refill
    }

    // --- Stage GEMM2 C into R3 (mid consumed) and LN2 epilogue
    stage_c(c2F, acc);     // includes sync

    {
        int row = row0 + lrow;
        if (row < R_TOTAL) {
            const float* Cr = c2F + lrow * CS_STRIDE + half * 64;
            const float* hr = hF + lrow * CS_STRIDE + half * 64;
            const float* br = b2 + half * 64;
            float s1 = 0.f, s2 = 0.f;
            #pragma unroll
            for (int c = 0; c < 64; c += 4) {
                float4 cv = *(const float4*)(Cr + c);
                float4 rv = *(const float4*)(hr + c);
                float4 bv = *(const float4*)(br + c);
                float v0 = cv.x + bv.x + rv.x;
                float v1 = cv.y + bv.y + rv.y;
                float v2 = cv.z + bv.z + rv.z;
                float v3 = cv.w + bv.w + rv.w;
                s1 += (v0 + v1) + (v2 + v3);
                s2 += (v0 * v0 + v1 * v1) + (v2 * v2 + v3 * v3);
            }
            s1 += __shfl_xor_sync(0xffffffffu, s1, 1);
            s2 += __shfl_xor_sync(0xffffffffu, s2, 1);
            float mean = s1 * (1.f / 128.f);
            float var  = s2 * (1.f / 128.f) - mean * mean;
            float rstd = rsqrtf(var + 1e-5f);
            float* orow = out + (size_t)row * D_DIM + half * 64;
            const float* gr = g2 + half * 64;
            const float* btr = bt2 + half * 64;
            #pragma unroll
            for (int c = 0; c < 64; c += 4) {
                float4 cv = *(const float4*)(Cr + c);
                float4 rv = *(const float4*)(hr + c);
                float4 bv = *(const float4*)(br + c);
                float4 gv = *(const float4*)(gr + c);
                float4 bb = *(const float4*)(btr + c);
                float4 o;
                o.x = (cv.x + bv.x + rv.x - mean) * rstd * gv.x + bb.x;
                o.y = (cv.y + bv.y + rv.y - mean) * rstd * gv.y + bb.y;
                o.z = (cv.z + bv.z + rv.z - mean) * rstd * gv.z + bb.z;
                o.w = (cv.w + bv.w + rv.w - mean) * rstd * gv.w + bb.w;
                *(float4*)(orow + c) = o;
            }
        } else {
            float s1 = 0.f, s2 = 0.f;
            s1 += __shfl_xor_sync(0xffffffffu, s1, 1);
            s2 += __shfl_xor_sync(0xffffffffu, s2, 1);
            (void)s1; (void)s2;
        }
    }
}

// ---------------------------------------------------------------------------
extern "C" void kernel_launch(void* const* d_in, const int* in_sizes, int n_in,
                              void* d_out, int out_size) {
    const float* x     = (const float*)d_in[0];
    const float* Wq    = (const float*)d_in[1];
    const float* bq    = (const float*)d_in[2];
    const float* Wk    = (const float*)d_in[3];
    const float* bk    = (const float*)d_in[4];
    const float* Wv    = (const float*)d_in[5];
    const float* bv    = (const float*)d_in[6];
    const float* Wo    = (const float*)d_in[7];
    const float* bo    = (const float*)d_in[8];
    const float* ln1_g = (const float*)d_in[9];
    const float* ln1_b = (const float*)d_in[10];
    const float* W1    = (const float*)d_in[11];
    const float* b1    = (const float*)d_in[12];
    const float* W2    = (const float*)d_in[13];
    const float* b2    = (const float*)d_in[14];
    const float* ln2_g = (const float*)d_in[15];
    const float* ln2_b = (const float*)d_in[16];
    float* out = (float*)d_out;

    cudaFuncSetAttribute(k_qkv,    cudaFuncAttributeMaxDynamicSharedMemorySize, QKV_SMEM);
    cudaFuncSetAttribute(k_block2, cudaFuncAttributeMaxDynamicSharedMemorySize, FB_SMEM);

    k_cvt_w<<<64, 512>>>(Wq, Wk, Wv, Wo, W1, W2);
    k_qkv<<<dim3(M_TILES, 3), 256, QKV_SMEM>>>(x, bq, bk, bv);
    attn_kernel<<<NB * H_HEADS * TT, 256>>>();
    k_block2<<<M_TILES, 256, FB_SMEM>>>(x, bo, ln1_g, ln1_b, b1, b2, ln2_g, ln2_b, out);
}